// round 2
// baseline (speedup 1.0000x reference)
#include <cuda_runtime.h>
#include <cstdint>
#include <math.h>

// Problem constants
#define NB 32
#define NS 1024
#define NC 12
#define NE 256
#define NH 512
#define NT 50
#define NBS (NB*NS)      // 32768 words

// ---------------- device scratch (no cudaMalloc allowed) ----------------
__device__ float g_cproj[128 * 4 * NE];            // [128][1024] char input proj (+bc)
__device__ float g_hc[NBS * NE];                   // char LSTM h  (final = char_feat)
__device__ float g_cc[NBS * NE];                   // char LSTM c
__device__ float g_gates[NBS * 4 * NE];            // char gates scratch
__device__ float g_xw[NBS * 2 * NE];               // [we ; char_feat]
__device__ float g_gin[NBS * 4 * NH];              // word input projection
__device__ float g_whs[NS * NB * NH];              // word hidden trace [t][b][h]
__device__ unsigned int g_bar;                     // grid barrier counter

__device__ __forceinline__ float sigm(float x) { return 1.0f / (1.0f + expf(-x)); }

// ---------------- init: zero char cell state + barrier ----------------
__global__ void init_kernel() {
    int idx = blockIdx.x * blockDim.x + threadIdx.x;
    if (idx < NBS * NE / 4)
        ((float4*)g_cc)[idx] = make_float4(0.f, 0.f, 0.f, 0.f);
    if (idx == 0) g_bar = 0u;
}

// ---------------- cproj[c][n] = bc[n] + char_emb[c,:] . Wc_ih[n,:] ----------------
__global__ void cproj_kernel(const float* __restrict__ char_emb,
                             const float* __restrict__ Wc_ih,
                             const float* __restrict__ bc) {
    __shared__ float ce[NE];
    int c = blockIdx.x;
    for (int i = threadIdx.x; i < NE; i += blockDim.x) ce[i] = char_emb[c * NE + i];
    __syncthreads();
    for (int n = threadIdx.x; n < 4 * NE; n += blockDim.x) {
        const float* wr = Wc_ih + (size_t)n * NE;
        float acc = bc[n];
        #pragma unroll 4
        for (int k = 0; k < NE; k++) acc += ce[k] * wr[k];
        g_cproj[c * 4 * NE + n] = acc;
    }
}

// ---------------- t=0 char gates: pure gather (h=0) ----------------
__global__ void gather_gates0_kernel(const int* __restrict__ char_idx) {
    int idx = blockIdx.x * blockDim.x + threadIdx.x;   // over NBS*256 float4
    int w = idx >> 8, q = idx & 255;
    int ci = char_idx[w * NC];
    ((float4*)g_gates)[(size_t)w * 256 + q] = ((const float4*)g_cproj)[(size_t)ci * 256 + q];
}

// ---------------- char LSTM cell update (elementwise) ----------------
__global__ void char_cell_kernel() {
    int idx = blockIdx.x * blockDim.x + threadIdx.x;   // NBS*64 float4 lanes
    int w = idx >> 6, q = idx & 63;
    const float4* gr = (const float4*)(g_gates + (size_t)w * 1024);
    float4 gi = gr[q], gf = gr[64 + q], gg = gr[128 + q], go = gr[192 + q];
    float4* cp = (float4*)(g_cc + (size_t)w * 256);
    float4 c = cp[q];
    float4 h;
    c.x = sigm(gf.x) * c.x + sigm(gi.x) * tanhf(gg.x); h.x = sigm(go.x) * tanhf(c.x);
    c.y = sigm(gf.y) * c.y + sigm(gi.y) * tanhf(gg.y); h.y = sigm(go.y) * tanhf(c.y);
    c.z = sigm(gf.z) * c.z + sigm(gi.z) * tanhf(gg.z); h.z = sigm(go.z) * tanhf(c.z);
    c.w = sigm(gf.w) * c.w + sigm(gi.w) * tanhf(gg.w); h.w = sigm(go.w) * tanhf(c.w);
    cp[q] = c;
    ((float4*)(g_hc + (size_t)w * 256))[q] = h;
}

// ---------------- generic SGEMM: C[M,N] = A[M,K] @ B[N,K]^T (+bias[n]) (+addrows[addidx[m]][n]) ----------------
// BM=128 BN=128 BK=8, 256 threads, 8x8 per thread. M,N mult of 128; K mult of 8.
__global__ __launch_bounds__(256, 2)
void gemm_nt_kernel(const float* __restrict__ A, const float* __restrict__ B,
                    float* __restrict__ C, int M, int N, int K,
                    const float* __restrict__ bias,
                    const float* __restrict__ addrows,
                    const int* __restrict__ addidx, int idx_stride) {
    __shared__ float As[8][128];
    __shared__ float Bs[8][128];
    int tid = threadIdx.x;
    int tx = tid & 15, ty = tid >> 4;
    int m0 = blockIdx.y * 128, n0 = blockIdx.x * 128;
    int lr = tid >> 1, lseg = (tid & 1) * 4;
    const float* Ag = A + (size_t)(m0 + lr) * K + lseg;
    const float* Bg = B + (size_t)(n0 + lr) * K + lseg;

    float acc[8][8];
    #pragma unroll
    for (int i = 0; i < 8; i++)
        #pragma unroll
        for (int j = 0; j < 8; j++) acc[i][j] = 0.f;

    float4 av = *(const float4*)(Ag);
    float4 bv = *(const float4*)(Bg);
    for (int kt = 0; kt < K; kt += 8) {
        As[lseg + 0][lr] = av.x; As[lseg + 1][lr] = av.y;
        As[lseg + 2][lr] = av.z; As[lseg + 3][lr] = av.w;
        Bs[lseg + 0][lr] = bv.x; Bs[lseg + 1][lr] = bv.y;
        Bs[lseg + 2][lr] = bv.z; Bs[lseg + 3][lr] = bv.w;
        __syncthreads();
        float4 av2 = make_float4(0, 0, 0, 0), bv2 = make_float4(0, 0, 0, 0);
        if (kt + 8 < K) {
            av2 = *(const float4*)(Ag + kt + 8);
            bv2 = *(const float4*)(Bg + kt + 8);
        }
        #pragma unroll
        for (int k = 0; k < 8; k++) {
            float a[8], bb[8];
            *(float4*)&a[0] = *(const float4*)&As[k][ty * 8];
            *(float4*)&a[4] = *(const float4*)&As[k][ty * 8 + 4];
            *(float4*)&bb[0] = *(const float4*)&Bs[k][tx * 8];
            *(float4*)&bb[4] = *(const float4*)&Bs[k][tx * 8 + 4];
            #pragma unroll
            for (int i = 0; i < 8; i++)
                #pragma unroll
                for (int j = 0; j < 8; j++) acc[i][j] += a[i] * bb[j];
        }
        __syncthreads();
        av = av2; bv = bv2;
    }

    #pragma unroll
    for (int i = 0; i < 8; i++) {
        int m = m0 + ty * 8 + i;
        const float* arow = nullptr;
        if (addrows) {
            int r = addidx[(size_t)m * idx_stride];
            arow = addrows + (size_t)r * N;
        }
        float* crow = C + (size_t)m * N + n0 + tx * 8;
        #pragma unroll
        for (int jj = 0; jj < 8; jj += 4) {
            float4 v = make_float4(acc[i][jj], acc[i][jj + 1], acc[i][jj + 2], acc[i][jj + 3]);
            if (bias) {
                float4 b4 = *(const float4*)(bias + n0 + tx * 8 + jj);
                v.x += b4.x; v.y += b4.y; v.z += b4.z; v.w += b4.w;
            }
            if (arow) {
                float4 a4 = *(const float4*)(arow + n0 + tx * 8 + jj);
                v.x += a4.x; v.y += a4.y; v.z += a4.z; v.w += a4.w;
            }
            *(float4*)(crow + jj) = v;
        }
    }
}

// ---------------- gather word-LSTM input x = [word_emb[idx] ; char_feat] ----------------
__global__ void gather_xw_kernel(const int* __restrict__ word_idx,
                                 const float* __restrict__ word_emb) {
    int idx = blockIdx.x * blockDim.x + threadIdx.x;   // NBS*128 float4
    int w = idx >> 7, q = idx & 127;
    float4 v;
    if (q < 64)
        v = ((const float4*)(word_emb + (size_t)word_idx[w] * NE))[q];
    else
        v = ((const float4*)(g_hc + (size_t)w * NE))[q - 64];
    ((float4*)(g_xw + (size_t)w * 512))[q] = v;
}

// ---------------- persistent word LSTM: 1024 steps, grid barrier ----------------
// 128 blocks x 128 threads. Block owns 4 hidden units; thread = (b, u_local),
// computes all 4 gate dot-products (K=512) and the cell update; c stays in a register.
__global__ void word_lstm_kernel(const float* __restrict__ Whh) {
    extern __shared__ float sm[];
    float* w_s = sm;              // [16][512] Whh rows for this block's 4 units x 4 gates
    float* h_s = sm + 16 * 512;   // [32][516] padded h
    const int tid = threadIdx.x;
    const int b = tid >> 2, ul = tid & 3;
    const int u = blockIdx.x * 4 + ul;

    for (int i = tid; i < 16 * 512; i += 128) {
        int r = i >> 9, k = i & 511;
        int grow = (r >> 2) * NH + blockIdx.x * 4 + (r & 3);   // gate*512 + unit
        w_s[i] = Whh[(size_t)grow * NH + k];
    }

    const float* wp0 = w_s + (0 + ul) * 512;
    const float* wp1 = w_s + (4 + ul) * 512;
    const float* wp2 = w_s + (8 + ul) * 512;
    const float* wp3 = w_s + (12 + ul) * 512;

    float c = 0.f;
    unsigned target = 0;
    for (int t = 0; t < NS; ++t) {
        if (t == 0) {
            for (int i = tid; i < 32 * 128; i += 128) {
                int bb = i >> 7, kq = i & 127;
                *(float4*)(h_s + bb * 516 + kq * 4) = make_float4(0, 0, 0, 0);
            }
        } else {
            const float* hp = g_whs + (size_t)(t - 1) * NB * NH;
            for (int i = tid; i < 32 * 128; i += 128) {
                int bb = i >> 7, kq = i & 127;
                *(float4*)(h_s + bb * 516 + kq * 4) = *(const float4*)(hp + bb * 512 + kq * 4);
            }
        }
        __syncthreads();

        float a0 = 0.f, a1 = 0.f, a2 = 0.f, a3 = 0.f;
        const float* hr = h_s + b * 516;
        #pragma unroll 4
        for (int k = 0; k < 512; k += 4) {
            float4 hv = *(const float4*)(hr + k);
            float4 w0 = *(const float4*)(wp0 + k);
            float4 w1 = *(const float4*)(wp1 + k);
            float4 w2 = *(const float4*)(wp2 + k);
            float4 w3 = *(const float4*)(wp3 + k);
            a0 += hv.x * w0.x + hv.y * w0.y + hv.z * w0.z + hv.w * w0.w;
            a1 += hv.x * w1.x + hv.y * w1.y + hv.z * w1.z + hv.w * w1.w;
            a2 += hv.x * w2.x + hv.y * w2.y + hv.z * w2.z + hv.w * w2.w;
            a3 += hv.x * w3.x + hv.y * w3.y + hv.z * w3.z + hv.w * w3.w;
        }

        const float* gin = g_gin + ((size_t)b * NS + t) * (4 * NH);
        float iv = sigm(a0 + gin[u]);
        float fv = sigm(a1 + gin[NH + u]);
        float gv = tanhf(a2 + gin[2 * NH + u]);
        float ov = sigm(a3 + gin[3 * NH + u]);
        c = fv * c + iv * gv;
        float h = ov * tanhf(c);
        g_whs[(size_t)t * NB * NH + b * NH + u] = h;

        __threadfence();
        __syncthreads();
        target += gridDim.x;
        if (tid == 0) {
            atomicAdd(&g_bar, 1u);
            while (atomicAdd(&g_bar, 0u) < target) { }
            __threadfence();
        }
        __syncthreads();
    }
}

// ---------------- tag projection + log_softmax ----------------
// block = 256 threads (8 warps), 8 tokens per block; warp w handles token w.
__global__ void tag_kernel(const float* __restrict__ Wt, const float* __restrict__ bt,
                           float* __restrict__ out) {
    __shared__ float hs[8][512];
    __shared__ float lg[8][52];
    int tid = threadIdx.x, warp = tid >> 5, lane = tid & 31;
    int wbase = blockIdx.x * 8;

    for (int i = tid; i < 8 * 512; i += 256) {
        int tok = i >> 9, k = i & 511;
        int w = wbase + tok;
        int b = w >> 10, s = w & 1023;
        hs[tok][k] = g_whs[((size_t)s * NB + b) * NH + k];
    }
    __syncthreads();

    for (int tg = 0; tg < NT; ++tg) {
        const float* wr = Wt + (size_t)tg * NH;
        float p = 0.f;
        for (int k = lane; k < NH; k += 32) p += hs[warp][k] * wr[k];
        #pragma unroll
        for (int o = 16; o; o >>= 1) p += __shfl_xor_sync(0xffffffff, p, o);
        if (lane == 0) lg[warp][tg] = p + bt[tg];
    }
    __syncwarp();

    float v0 = (lane < NT) ? lg[warp][lane] : -1e30f;
    float v1 = (lane + 32 < NT) ? lg[warp][lane + 32] : -1e30f;
    float m = fmaxf(v0, v1);
    #pragma unroll
    for (int o = 16; o; o >>= 1) m = fmaxf(m, __shfl_xor_sync(0xffffffff, m, o));
    float e = ((lane < NT) ? expf(v0 - m) : 0.f) + ((lane + 32 < NT) ? expf(v1 - m) : 0.f);
    #pragma unroll
    for (int o = 16; o; o >>= 1) e += __shfl_xor_sync(0xffffffff, e, o);
    float lse = m + logf(e);

    int w = wbase + warp;
    if (lane < NT)      out[(size_t)w * NT + lane]      = v0 - lse;
    if (lane + 32 < NT) out[(size_t)w * NT + lane + 32] = v1 - lse;
}

// ---------------- host entry ----------------
extern "C" void kernel_launch(void* const* d_in, const int* in_sizes, int n_in,
                              void* d_out, int out_size) {
    const int*   char_idx = (const int*)d_in[0];
    const int*   word_idx = (const int*)d_in[1];
    const float* char_emb = (const float*)d_in[2];
    const float* word_emb = (const float*)d_in[3];
    const float* Wc_ih    = (const float*)d_in[4];
    const float* Wc_hh    = (const float*)d_in[5];
    const float* bc       = (const float*)d_in[6];
    const float* Ww_ih    = (const float*)d_in[7];
    const float* Ww_hh    = (const float*)d_in[8];
    const float* bw       = (const float*)d_in[9];
    const float* Wt       = (const float*)d_in[10];
    const float* bt       = (const float*)d_in[11];
    float* out = (float*)d_out;

    float *p_hc, *p_gates, *p_xw, *p_gin, *p_cproj;
    cudaGetSymbolAddress((void**)&p_hc,    g_hc);
    cudaGetSymbolAddress((void**)&p_gates, g_gates);
    cudaGetSymbolAddress((void**)&p_xw,    g_xw);
    cudaGetSymbolAddress((void**)&p_gin,   g_gin);
    cudaGetSymbolAddress((void**)&p_cproj, g_cproj);

    init_kernel<<<8192, 256>>>();
    cproj_kernel<<<128, 256>>>(char_emb, Wc_ih, bc);

    // char LSTM: t=0 is a pure gather (h=0), then 11 recurrent GEMM+cell steps
    gather_gates0_kernel<<<NBS, 256>>>(char_idx);
    char_cell_kernel<<<8192, 256>>>();
    for (int t = 1; t < NC; t++) {
        gemm_nt_kernel<<<dim3(1024 / 128, NBS / 128), 256>>>(
            p_hc, Wc_hh, p_gates, NBS, 1024, 256,
            nullptr, p_cproj, char_idx + t, NC);
        char_cell_kernel<<<8192, 256>>>();
    }

    // word input projection
    gather_xw_kernel<<<NBS * 128 / 256, 256>>>(word_idx, word_emb);
    gemm_nt_kernel<<<dim3(2048 / 128, NBS / 128), 256>>>(
        p_xw, Ww_ih, p_gin, NBS, 2048, 512, bw, nullptr, nullptr, 0);

    // persistent word LSTM (1024 steps, internal grid barrier)
    cudaFuncSetAttribute(word_lstm_kernel,
                         cudaFuncAttributeMaxDynamicSharedMemorySize, 98816);
    word_lstm_kernel<<<128, 128, 98816>>>(Ww_hh);

    // tag projection + log_softmax
    tag_kernel<<<NBS / 8, 256>>>(Wt, bt, out);
}

// round 4
// speedup vs baseline: 1.1183x; 1.1183x over previous
#include <cuda_runtime.h>
#include <cuda_bf16.h>
#include <cstdint>
#include <math.h>

// Problem constants
#define NB 32
#define NS 1024
#define NC 12
#define NE 256
#define NH 512
#define NT 50
#define NBS (NB*NS)      // 32768 words

// ---------------- device scratch (no cudaMalloc allowed) ----------------
__device__ float g_cproj[128 * 4 * NE];              // [128][1024] char input proj (+bc)
__device__ float g_hc[NBS * NE];                     // char LSTM h (fp32)
__device__ float g_cc[NBS * NE];                     // char LSTM c
__device__ float g_gates[NBS * 4 * NE];              // char gates scratch
__device__ __nv_bfloat16 g_h3[NBS * 3 * NE];         // h triple bf16 [hi,lo,hi]
__device__ __nv_bfloat16 g_wchh3[4 * NE * 3 * NE];   // Wc_hh triple [hi,hi,lo]
__device__ __nv_bfloat16 g_xw3[NBS * 3 * 2 * NE];    // [we;char_feat] triple [hi,lo,hi]
__device__ __nv_bfloat16 g_wwih3[4 * NH * 3 * 2 * NE]; // Ww_ih triple [hi,hi,lo]
__device__ float g_gin[NBS * 4 * NH];                // word input projection
__device__ float g_whs[NS * NB * NH];                // word hidden trace [t][b][h]
__device__ unsigned int g_bar;                       // grid barrier counter

__device__ __forceinline__ float sigm(float x) { return 1.0f / (1.0f + expf(-x)); }

// ---------------- init: zero char cell state + barrier ----------------
__global__ void init_kernel() {
    int idx = blockIdx.x * blockDim.x + threadIdx.x;
    if (idx < NBS * NE / 4)
        ((float4*)g_cc)[idx] = make_float4(0.f, 0.f, 0.f, 0.f);
    if (idx == 0) g_bar = 0u;
}

// ---------------- cproj[c][n] = bc[n] + char_emb[c,:] . Wc_ih[n,:] ----------------
__global__ void cproj_kernel(const float* __restrict__ char_emb,
                             const float* __restrict__ Wc_ih,
                             const float* __restrict__ bc) {
    __shared__ float ce[NE];
    int c = blockIdx.x;
    for (int i = threadIdx.x; i < NE; i += blockDim.x) ce[i] = char_emb[c * NE + i];
    __syncthreads();
    for (int n = threadIdx.x; n < 4 * NE; n += blockDim.x) {
        const float* wr = Wc_ih + (size_t)n * NE;
        float acc = bc[n];
        #pragma unroll 4
        for (int k = 0; k < NE; k++) acc += ce[k] * wr[k];
        g_cproj[c * 4 * NE + n] = acc;
    }
}

// ---------------- fp32 -> triple bf16 conversion ----------------
// mode 0 (A-side): [hi, lo, hi]   mode 1 (B-side): [hi, hi, lo]
__global__ void convert3_kernel(const float* __restrict__ src,
                                __nv_bfloat16* __restrict__ dst,
                                int n8, int mode) {
    int idx = blockIdx.x * blockDim.x + threadIdx.x;
    if (idx >= n8) return;
    float4 s0 = ((const float4*)src)[idx * 2];
    float4 s1 = ((const float4*)src)[idx * 2 + 1];
    float v[8] = {s0.x, s0.y, s0.z, s0.w, s1.x, s1.y, s1.z, s1.w};
    unsigned short o[24];
    #pragma unroll
    for (int j = 0; j < 8; j++) {
        __nv_bfloat16 hi = __float2bfloat16(v[j]);
        __nv_bfloat16 lo = __float2bfloat16(v[j] - __bfloat162float(hi));
        unsigned short hb = __bfloat16_as_ushort(hi), lb = __bfloat16_as_ushort(lo);
        if (mode == 0) { o[3*j] = hb; o[3*j+1] = lb; o[3*j+2] = hb; }
        else           { o[3*j] = hb; o[3*j+1] = hb; o[3*j+2] = lb; }
    }
    uint4* dp = (uint4*)(dst + (size_t)idx * 24);
    const uint4* op = (const uint4*)o;
    dp[0] = op[0]; dp[1] = op[1]; dp[2] = op[2];
}

// ---------------- t=0 char gates: pure gather (h=0) ----------------
__global__ void gather_gates0_kernel(const int* __restrict__ char_idx) {
    int idx = blockIdx.x * blockDim.x + threadIdx.x;   // over NBS*256 float4
    int w = idx >> 8, q = idx & 255;
    int ci = char_idx[w * NC];
    ((float4*)g_gates)[(size_t)w * 256 + q] = ((const float4*)g_cproj)[(size_t)ci * 256 + q];
}

// ---------------- char LSTM cell update + triple-bf16 h emit ----------------
__global__ void char_cell_kernel() {
    int idx = blockIdx.x * blockDim.x + threadIdx.x;   // NBS*32 threads, 8 units each
    int w = idx >> 5, q = idx & 31;
    const float* gp = g_gates + (size_t)w * 1024 + q * 8;
    float4 i0 = *(const float4*)(gp);        float4 i1 = *(const float4*)(gp + 4);
    float4 f0 = *(const float4*)(gp + 256);  float4 f1 = *(const float4*)(gp + 260);
    float4 g0 = *(const float4*)(gp + 512);  float4 g1 = *(const float4*)(gp + 516);
    float4 o0 = *(const float4*)(gp + 768);  float4 o1 = *(const float4*)(gp + 772);
    float* cp = g_cc + (size_t)w * 256 + q * 8;
    float4 c0 = *(const float4*)(cp);        float4 c1 = *(const float4*)(cp + 4);
    float gi[8] = {i0.x,i0.y,i0.z,i0.w,i1.x,i1.y,i1.z,i1.w};
    float gf[8] = {f0.x,f0.y,f0.z,f0.w,f1.x,f1.y,f1.z,f1.w};
    float gg[8] = {g0.x,g0.y,g0.z,g0.w,g1.x,g1.y,g1.z,g1.w};
    float go[8] = {o0.x,o0.y,o0.z,o0.w,o1.x,o1.y,o1.z,o1.w};
    float cc[8] = {c0.x,c0.y,c0.z,c0.w,c1.x,c1.y,c1.z,c1.w};
    float h[8];
    #pragma unroll
    for (int j = 0; j < 8; j++) {
        cc[j] = sigm(gf[j]) * cc[j] + sigm(gi[j]) * tanhf(gg[j]);
        h[j] = sigm(go[j]) * tanhf(cc[j]);
    }
    *(float4*)(cp)     = make_float4(cc[0],cc[1],cc[2],cc[3]);
    *(float4*)(cp + 4) = make_float4(cc[4],cc[5],cc[6],cc[7]);
    float* hp = g_hc + (size_t)w * 256 + q * 8;
    *(float4*)(hp)     = make_float4(h[0],h[1],h[2],h[3]);
    *(float4*)(hp + 4) = make_float4(h[4],h[5],h[6],h[7]);
    unsigned short o[24];
    #pragma unroll
    for (int j = 0; j < 8; j++) {
        __nv_bfloat16 hi = __float2bfloat16(h[j]);
        __nv_bfloat16 lo = __float2bfloat16(h[j] - __bfloat162float(hi));
        o[3*j] = __bfloat16_as_ushort(hi);
        o[3*j+1] = __bfloat16_as_ushort(lo);
        o[3*j+2] = __bfloat16_as_ushort(hi);
    }
    uint4* dp = (uint4*)(g_h3 + (size_t)w * 768 + q * 24);
    const uint4* op = (const uint4*)o;
    dp[0] = op[0]; dp[1] = op[1]; dp[2] = op[2];
}

// ---------------- bf16 tensor-core GEMM: C[M,N] = A[M,K]@B[N,K]^T (+bias)(+addrows gather) ----------------
// CTA 128x128, K-tile 64, 8 warps (2x4), warp tile 64x32, mma.m16n8k16 bf16.
#define KT 64
#define SROW 72   // padded smem row (bf16 elems), 144B stride

__device__ __forceinline__ void mma16816(float* d, const uint32_t* a, const uint32_t* b) {
    asm volatile(
        "mma.sync.aligned.m16n8k16.row.col.f32.bf16.bf16.f32 "
        "{%0,%1,%2,%3}, {%4,%5,%6,%7}, {%8,%9}, {%0,%1,%2,%3};"
        : "+f"(d[0]), "+f"(d[1]), "+f"(d[2]), "+f"(d[3])
        : "r"(a[0]), "r"(a[1]), "r"(a[2]), "r"(a[3]), "r"(b[0]), "r"(b[1]));
}

__global__ __launch_bounds__(256)
void mma_gemm_kernel(const __nv_bfloat16* __restrict__ A,
                     const __nv_bfloat16* __restrict__ B,
                     float* __restrict__ C,
                     int M, int N, int K,
                     const float* __restrict__ bias,
                     const float* __restrict__ addrows,
                     const int* __restrict__ addidx, int idx_stride) {
    extern __shared__ __nv_bfloat16 smem[];
    __nv_bfloat16* As = smem;                    // [2][128][SROW]
    __nv_bfloat16* Bs = smem + 2 * 128 * SROW;   // [2][128][SROW]
    const int tid = threadIdx.x;
    const int m0 = blockIdx.y * 128, n0 = blockIdx.x * 128;
    const int lane = tid & 31, wid = tid >> 5;
    const int wm = wid >> 2, wn = wid & 3;       // 2 x 4 warp grid
    const int r = lane >> 2, cp2 = (lane & 3) * 2;

    float acc[4][4][4];
    #pragma unroll
    for (int i = 0; i < 4; i++)
        #pragma unroll
        for (int j = 0; j < 4; j++)
            #pragma unroll
            for (int q = 0; q < 4; q++) acc[i][j][q] = 0.f;

    // 2048 16B chunks per stage (A tile 1024 + B tile 1024), 256 threads x 8
    #define STAGE_LOAD(s, kt) do {                                                  \
        _Pragma("unroll")                                                           \
        for (int j = 0; j < 8; j++) {                                               \
            int ch = tid + j * 256;                                                 \
            int isB = ch >> 10; int c2 = ch & 1023;                                 \
            int row = c2 >> 3, kc = c2 & 7;                                         \
            const __nv_bfloat16* gp = (isB ? B + (size_t)(n0 + row) * K             \
                                           : A + (size_t)(m0 + row) * K)            \
                                      + (kt) + kc * 8;                              \
            __nv_bfloat16* sp = (isB ? Bs : As) + (s) * (128 * SROW)                \
                                + row * SROW + kc * 8;                              \
            uint32_t saddr = (uint32_t)__cvta_generic_to_shared(sp);                \
            asm volatile("cp.async.cg.shared.global [%0], [%1], 16;\n"              \
                         :: "r"(saddr), "l"(gp));                                   \
        }                                                                           \
        asm volatile("cp.async.commit_group;\n");                                   \
    } while (0)

    STAGE_LOAD(0, 0);
    const int nk = K / KT;
    for (int kt = 0; kt < nk; kt++) {
        if (kt + 1 < nk) {
            STAGE_LOAD((kt + 1) & 1, (kt + 1) * KT);
            asm volatile("cp.async.wait_group 1;\n");
        } else {
            asm volatile("cp.async.wait_group 0;\n");
        }
        __syncthreads();

        const __nv_bfloat16* At = As + (kt & 1) * (128 * SROW) + (wm * 64) * SROW;
        const __nv_bfloat16* Bt = Bs + (kt & 1) * (128 * SROW) + (wn * 32) * SROW;
        #pragma unroll
        for (int k16 = 0; k16 < KT; k16 += 16) {
            uint32_t a[4][4], b[4][2];
            #pragma unroll
            for (int mi = 0; mi < 4; mi++) {
                const __nv_bfloat16* ap = At + (mi * 16 + r) * SROW + k16 + cp2;
                a[mi][0] = *(const uint32_t*)(ap);
                a[mi][1] = *(const uint32_t*)(ap + 8 * SROW);
                a[mi][2] = *(const uint32_t*)(ap + 8);
                a[mi][3] = *(const uint32_t*)(ap + 8 * SROW + 8);
            }
            #pragma unroll
            for (int nj = 0; nj < 4; nj++) {
                const __nv_bfloat16* bp = Bt + (nj * 8 + r) * SROW + k16 + cp2;
                b[nj][0] = *(const uint32_t*)(bp);
                b[nj][1] = *(const uint32_t*)(bp + 8);
            }
            #pragma unroll
            for (int mi = 0; mi < 4; mi++)
                #pragma unroll
                for (int nj = 0; nj < 4; nj++)
                    mma16816(acc[mi][nj], a[mi], b[nj]);
        }
        __syncthreads();
    }

    // epilogue
    #pragma unroll
    for (int mi = 0; mi < 4; mi++) {
        int row0 = m0 + wm * 64 + mi * 16 + r;
        int row1 = row0 + 8;
        const float* ar0 = nullptr;
        const float* ar1 = nullptr;
        if (addrows) {
            ar0 = addrows + (size_t)addidx[(size_t)row0 * idx_stride] * N;
            ar1 = addrows + (size_t)addidx[(size_t)row1 * idx_stride] * N;
        }
        #pragma unroll
        for (int nj = 0; nj < 4; nj++) {
            int col = n0 + wn * 32 + nj * 8 + cp2;
            float v0 = acc[mi][nj][0], v1 = acc[mi][nj][1];
            float v2 = acc[mi][nj][2], v3 = acc[mi][nj][3];
            if (bias) {
                float2 b2 = *(const float2*)(bias + col);
                v0 += b2.x; v1 += b2.y; v2 += b2.x; v3 += b2.y;
            }
            if (ar0) {
                float2 a0 = *(const float2*)(ar0 + col);
                float2 a1 = *(const float2*)(ar1 + col);
                v0 += a0.x; v1 += a0.y; v2 += a1.x; v3 += a1.y;
            }
            *(float2*)(C + (size_t)row0 * N + col) = make_float2(v0, v1);
            *(float2*)(C + (size_t)row1 * N + col) = make_float2(v2, v3);
        }
    }
}

// ---------------- gather word-LSTM input -> triple bf16 directly ----------------
__global__ void gather_xw3_kernel(const int* __restrict__ word_idx,
                                  const float* __restrict__ word_emb) {
    int idx = blockIdx.x * blockDim.x + threadIdx.x;   // NBS*64, 8 elems each
    int w = idx >> 6, q = idx & 63;
    const float* src = (q < 32)
        ? word_emb + (size_t)word_idx[w] * NE + q * 8
        : g_hc + (size_t)w * NE + (q - 32) * 8;
    float4 s0 = *(const float4*)(src);
    float4 s1 = *(const float4*)(src + 4);
    float v[8] = {s0.x, s0.y, s0.z, s0.w, s1.x, s1.y, s1.z, s1.w};
    unsigned short o[24];
    #pragma unroll
    for (int j = 0; j < 8; j++) {
        __nv_bfloat16 hi = __float2bfloat16(v[j]);
        __nv_bfloat16 lo = __float2bfloat16(v[j] - __bfloat162float(hi));
        o[3*j] = __bfloat16_as_ushort(hi);
        o[3*j+1] = __bfloat16_as_ushort(lo);
        o[3*j+2] = __bfloat16_as_ushort(hi);
    }
    uint4* dp = (uint4*)(g_xw3 + (size_t)w * 1536 + q * 24);
    const uint4* op = (const uint4*)o;
    dp[0] = op[0]; dp[1] = op[1]; dp[2] = op[2];
}

// ---------------- persistent word LSTM: 1024 steps, grid barrier ----------------
__global__ void word_lstm_kernel(const float* __restrict__ Whh) {
    extern __shared__ float sm[];
    float* w_s = sm;              // [16][512]
    float* h_s = sm + 16 * 512;   // [32][516]
    const int tid = threadIdx.x;
    const int b = tid >> 2, ul = tid & 3;
    const int u = blockIdx.x * 4 + ul;

    for (int i = tid; i < 16 * 512; i += 128) {
        int rr = i >> 9, k = i & 511;
        int grow = (rr >> 2) * NH + blockIdx.x * 4 + (rr & 3);
        w_s[i] = Whh[(size_t)grow * NH + k];
    }

    const float* wp0 = w_s + (0 + ul) * 512;
    const float* wp1 = w_s + (4 + ul) * 512;
    const float* wp2 = w_s + (8 + ul) * 512;
    const float* wp3 = w_s + (12 + ul) * 512;

    float c = 0.f;
    unsigned target = 0;
    for (int t = 0; t < NS; ++t) {
        if (t == 0) {
            for (int i = tid; i < 32 * 128; i += 128) {
                int bb = i >> 7, kq = i & 127;
                *(float4*)(h_s + bb * 516 + kq * 4) = make_float4(0, 0, 0, 0);
            }
        } else {
            const float* hp = g_whs + (size_t)(t - 1) * NB * NH;
            for (int i = tid; i < 32 * 128; i += 128) {
                int bb = i >> 7, kq = i & 127;
                *(float4*)(h_s + bb * 516 + kq * 4) = *(const float4*)(hp + bb * 512 + kq * 4);
            }
        }
        __syncthreads();

        float a0 = 0.f, a1 = 0.f, a2 = 0.f, a3 = 0.f;
        const float* hr = h_s + b * 516;
        #pragma unroll 4
        for (int k = 0; k < 512; k += 4) {
            float4 hv = *(const float4*)(hr + k);
            float4 w0 = *(const float4*)(wp0 + k);
            float4 w1 = *(const float4*)(wp1 + k);
            float4 w2 = *(const float4*)(wp2 + k);
            float4 w3 = *(const float4*)(wp3 + k);
            a0 += hv.x * w0.x + hv.y * w0.y + hv.z * w0.z + hv.w * w0.w;
            a1 += hv.x * w1.x + hv.y * w1.y + hv.z * w1.z + hv.w * w1.w;
            a2 += hv.x * w2.x + hv.y * w2.y + hv.z * w2.z + hv.w * w2.w;
            a3 += hv.x * w3.x + hv.y * w3.y + hv.z * w3.z + hv.w * w3.w;
        }

        const float* gin = g_gin + ((size_t)b * NS + t) * (4 * NH);
        float iv = sigm(a0 + gin[u]);
        float fv = sigm(a1 + gin[NH + u]);
        float gv = tanhf(a2 + gin[2 * NH + u]);
        float ov = sigm(a3 + gin[3 * NH + u]);
        c = fv * c + iv * gv;
        float h = ov * tanhf(c);
        g_whs[(size_t)t * NB * NH + b * NH + u] = h;

        __threadfence();
        __syncthreads();
        target += gridDim.x;
        if (tid == 0) {
            atomicAdd(&g_bar, 1u);
            while (atomicAdd(&g_bar, 0u) < target) { }
            __threadfence();
        }
        __syncthreads();
    }
}

// ---------------- tag projection + log_softmax ----------------
__global__ void tag_kernel(const float* __restrict__ Wt, const float* __restrict__ bt,
                           float* __restrict__ out) {
    __shared__ float hs[8][512];
    __shared__ float lg[8][52];
    int tid = threadIdx.x, warp = tid >> 5, lane = tid & 31;
    int wbase = blockIdx.x * 8;

    for (int i = tid; i < 8 * 512; i += 256) {
        int tok = i >> 9, k = i & 511;
        int w = wbase + tok;
        int b = w >> 10, s = w & 1023;
        hs[tok][k] = g_whs[((size_t)s * NB + b) * NH + k];
    }
    __syncthreads();

    for (int tg = 0; tg < NT; ++tg) {
        const float* wr = Wt + (size_t)tg * NH;
        float p = 0.f;
        for (int k = lane; k < NH; k += 32) p += hs[warp][k] * wr[k];
        #pragma unroll
        for (int o = 16; o; o >>= 1) p += __shfl_xor_sync(0xffffffff, p, o);
        if (lane == 0) lg[warp][tg] = p + bt[tg];
    }
    __syncwarp();

    float v0 = (lane < NT) ? lg[warp][lane] : -1e30f;
    float v1 = (lane + 32 < NT) ? lg[warp][lane + 32] : -1e30f;
    float m = fmaxf(v0, v1);
    #pragma unroll
    for (int o = 16; o; o >>= 1) m = fmaxf(m, __shfl_xor_sync(0xffffffff, m, o));
    float e = ((lane < NT) ? expf(v0 - m) : 0.f) + ((lane + 32 < NT) ? expf(v1 - m) : 0.f);
    #pragma unroll
    for (int o = 16; o; o >>= 1) e += __shfl_xor_sync(0xffffffff, e, o);
    float lse = m + logf(e);

    int w = wbase + warp;
    if (lane < NT)      out[(size_t)w * NT + lane]      = v0 - lse;
    if (lane + 32 < NT) out[(size_t)w * NT + lane + 32] = v1 - lse;
}

// ---------------- host entry ----------------
extern "C" void kernel_launch(void* const* d_in, const int* in_sizes, int n_in,
                              void* d_out, int out_size) {
    const int*   char_idx = (const int*)d_in[0];
    const int*   word_idx = (const int*)d_in[1];
    const float* char_emb = (const float*)d_in[2];
    const float* word_emb = (const float*)d_in[3];
    const float* Wc_ih    = (const float*)d_in[4];
    const float* Wc_hh    = (const float*)d_in[5];
    const float* bc       = (const float*)d_in[6];
    const float* Ww_ih    = (const float*)d_in[7];
    const float* Ww_hh    = (const float*)d_in[8];
    const float* bw       = (const float*)d_in[9];
    const float* Wt       = (const float*)d_in[10];
    const float* bt       = (const float*)d_in[11];
    float* out = (float*)d_out;

    float *p_gates, *p_gin, *p_cproj;
    __nv_bfloat16 *p_h3, *p_wchh3, *p_xw3, *p_wwih3;
    cudaGetSymbolAddress((void**)&p_gates, g_gates);
    cudaGetSymbolAddress((void**)&p_gin,   g_gin);
    cudaGetSymbolAddress((void**)&p_cproj, g_cproj);
    cudaGetSymbolAddress((void**)&p_h3,    g_h3);
    cudaGetSymbolAddress((void**)&p_wchh3, g_wchh3);
    cudaGetSymbolAddress((void**)&p_xw3,   g_xw3);
    cudaGetSymbolAddress((void**)&p_wwih3, g_wwih3);

    const int gemm_smem = 4 * 128 * SROW * 2;  // 73728 B
    cudaFuncSetAttribute(mma_gemm_kernel,
                         cudaFuncAttributeMaxDynamicSharedMemorySize, gemm_smem);
    cudaFuncSetAttribute(word_lstm_kernel,
                         cudaFuncAttributeMaxDynamicSharedMemorySize, 98816);

    init_kernel<<<8192, 256>>>();
    cproj_kernel<<<128, 256>>>(char_emb, Wc_ih, bc);

    // weight conversions (triple bf16, B-pattern)
    convert3_kernel<<<(4*NE*NE/8 + 255)/256, 256>>>(Wc_hh, p_wchh3, 4*NE*NE/8, 1);
    convert3_kernel<<<(4*NH*2*NE/8 + 255)/256, 256>>>(Ww_ih, p_wwih3, 4*NH*2*NE/8, 1);

    // char LSTM: t=0 is pure gather (h=0), then 11 recurrent steps on tensor cores
    gather_gates0_kernel<<<NBS, 256>>>(char_idx);
    char_cell_kernel<<<NBS*32/256, 256>>>();
    for (int t = 1; t < NC; t++) {
        mma_gemm_kernel<<<dim3(1024/128, NBS/128), 256, gemm_smem>>>(
            p_h3, p_wchh3, p_gates, NBS, 1024, 3*NE,
            nullptr, p_cproj, char_idx + t, NC);
        char_cell_kernel<<<NBS*32/256, 256>>>();
    }

    // word input projection on tensor cores
    gather_xw3_kernel<<<NBS*64/256, 256>>>(word_idx, word_emb);
    mma_gemm_kernel<<<dim3(2048/128, NBS/128), 256, gemm_smem>>>(
        p_xw3, p_wwih3, p_gin, NBS, 2048, 3*2*NE,
        bw, nullptr, nullptr, 0);

    // persistent word LSTM (1024 steps, internal grid barrier)
    word_lstm_kernel<<<128, 128, 98816>>>(Ww_hh);

    // tag projection + log_softmax
    tag_kernel<<<NBS/8, 256>>>(Wt, bt, out);
}

// round 8
// speedup vs baseline: 1.1390x; 1.0185x over previous
#include <cuda_runtime.h>
#include <cuda_bf16.h>
#include <cstdint>
#include <math.h>

// Problem constants
#define NB 32
#define NS 1024
#define NC 12
#define NE 256
#define NH 512
#define NT 50
#define NBS (NB*NS)      // 32768 words

// ---------------- device scratch (no cudaMalloc allowed) ----------------
__device__ float g_cproj[128 * 4 * NE];              // [128][1024] char input proj (+bc)
__device__ float g_hc[NBS * NE];                     // char LSTM h (fp32)
__device__ float g_cc[NBS * NE];                     // char LSTM c
__device__ float g_gates[NBS * 4 * NE];              // char gates scratch
__device__ __nv_bfloat16 g_h3[NBS * 3 * NE];         // h triple bf16 [hi,lo,hi]
__device__ __nv_bfloat16 g_wchh3[4 * NE * 3 * NE];   // Wc_hh triple [hi,hi,lo]
__device__ __nv_bfloat16 g_xw3[NBS * 3 * 2 * NE];    // [we;char_feat] triple [hi,lo,hi]
__device__ __nv_bfloat16 g_wwih3[4 * NH * 3 * 2 * NE]; // Ww_ih triple [hi,hi,lo]
__device__ float g_gin[NBS * 4 * NH];                // word input projection
__device__ float g_whs[NS * NB * NH];                // word hidden trace [t][b][h]
__device__ unsigned int g_bar;                       // grid barrier counter

__device__ __forceinline__ float sigm(float x) { return 1.0f / (1.0f + expf(-x)); }

// ---------------- init: zero char cell state + barrier ----------------
__global__ void init_kernel() {
    int idx = blockIdx.x * blockDim.x + threadIdx.x;
    if (idx < NBS * NE / 4)
        ((float4*)g_cc)[idx] = make_float4(0.f, 0.f, 0.f, 0.f);
    if (idx == 0) g_bar = 0u;
}

// ---------------- cproj[c][n] = bc[n] + char_emb[c,:] . Wc_ih[n,:] ----------------
__global__ void cproj_kernel(const float* __restrict__ char_emb,
                             const float* __restrict__ Wc_ih,
                             const float* __restrict__ bc) {
    __shared__ float ce[NE];
    int c = blockIdx.x;
    for (int i = threadIdx.x; i < NE; i += blockDim.x) ce[i] = char_emb[c * NE + i];
    __syncthreads();
    for (int n = threadIdx.x; n < 4 * NE; n += blockDim.x) {
        const float* wr = Wc_ih + (size_t)n * NE;
        float acc = bc[n];
        #pragma unroll 4
        for (int k = 0; k < NE; k++) acc += ce[k] * wr[k];
        g_cproj[c * 4 * NE + n] = acc;
    }
}

// ---------------- fp32 -> triple bf16 conversion ----------------
// mode 0 (A-side): [hi, lo, hi]   mode 1 (B-side): [hi, hi, lo]
__global__ void convert3_kernel(const float* __restrict__ src,
                                __nv_bfloat16* __restrict__ dst,
                                int n8, int mode) {
    int idx = blockIdx.x * blockDim.x + threadIdx.x;
    if (idx >= n8) return;
    float4 s0 = ((const float4*)src)[idx * 2];
    float4 s1 = ((const float4*)src)[idx * 2 + 1];
    float v[8] = {s0.x, s0.y, s0.z, s0.w, s1.x, s1.y, s1.z, s1.w};
    unsigned short o[24];
    #pragma unroll
    for (int j = 0; j < 8; j++) {
        __nv_bfloat16 hi = __float2bfloat16(v[j]);
        __nv_bfloat16 lo = __float2bfloat16(v[j] - __bfloat162float(hi));
        unsigned short hb = __bfloat16_as_ushort(hi), lb = __bfloat16_as_ushort(lo);
        if (mode == 0) { o[3*j] = hb; o[3*j+1] = lb; o[3*j+2] = hb; }
        else           { o[3*j] = hb; o[3*j+1] = hb; o[3*j+2] = lb; }
    }
    uint4* dp = (uint4*)(dst + (size_t)idx * 24);
    const uint4* op = (const uint4*)o;
    dp[0] = op[0]; dp[1] = op[1]; dp[2] = op[2];
}

// ---------------- t=0 char gates: pure gather (h=0) ----------------
__global__ void gather_gates0_kernel(const int* __restrict__ char_idx) {
    int idx = blockIdx.x * blockDim.x + threadIdx.x;   // over NBS*256 float4
    int w = idx >> 8, q = idx & 255;
    int ci = char_idx[w * NC];
    ((float4*)g_gates)[(size_t)w * 256 + q] = ((const float4*)g_cproj)[(size_t)ci * 256 + q];
}

// ---------------- char LSTM cell update + triple-bf16 h emit ----------------
__global__ void char_cell_kernel() {
    int idx = blockIdx.x * blockDim.x + threadIdx.x;   // NBS*32 threads, 8 units each
    int w = idx >> 5, q = idx & 31;
    const float* gp = g_gates + (size_t)w * 1024 + q * 8;
    float4 i0 = *(const float4*)(gp);        float4 i1 = *(const float4*)(gp + 4);
    float4 f0 = *(const float4*)(gp + 256);  float4 f1 = *(const float4*)(gp + 260);
    float4 g0 = *(const float4*)(gp + 512);  float4 g1 = *(const float4*)(gp + 516);
    float4 o0 = *(const float4*)(gp + 768);  float4 o1 = *(const float4*)(gp + 772);
    float* cp = g_cc + (size_t)w * 256 + q * 8;
    float4 c0 = *(const float4*)(cp);        float4 c1 = *(const float4*)(cp + 4);
    float gi[8] = {i0.x,i0.y,i0.z,i0.w,i1.x,i1.y,i1.z,i1.w};
    float gf[8] = {f0.x,f0.y,f0.z,f0.w,f1.x,f1.y,f1.z,f1.w};
    float gg[8] = {g0.x,g0.y,g0.z,g0.w,g1.x,g1.y,g1.z,g1.w};
    float go[8] = {o0.x,o0.y,o0.z,o0.w,o1.x,o1.y,o1.z,o1.w};
    float cc[8] = {c0.x,c0.y,c0.z,c0.w,c1.x,c1.y,c1.z,c1.w};
    float h[8];
    #pragma unroll
    for (int j = 0; j < 8; j++) {
        cc[j] = sigm(gf[j]) * cc[j] + sigm(gi[j]) * tanhf(gg[j]);
        h[j] = sigm(go[j]) * tanhf(cc[j]);
    }
    *(float4*)(cp)     = make_float4(cc[0],cc[1],cc[2],cc[3]);
    *(float4*)(cp + 4) = make_float4(cc[4],cc[5],cc[6],cc[7]);
    float* hp = g_hc + (size_t)w * 256 + q * 8;
    *(float4*)(hp)     = make_float4(h[0],h[1],h[2],h[3]);
    *(float4*)(hp + 4) = make_float4(h[4],h[5],h[6],h[7]);
    unsigned short o[24];
    #pragma unroll
    for (int j = 0; j < 8; j++) {
        __nv_bfloat16 hi = __float2bfloat16(h[j]);
        __nv_bfloat16 lo = __float2bfloat16(h[j] - __bfloat162float(hi));
        o[3*j] = __bfloat16_as_ushort(hi);
        o[3*j+1] = __bfloat16_as_ushort(lo);
        o[3*j+2] = __bfloat16_as_ushort(hi);
    }
    uint4* dp = (uint4*)(g_h3 + (size_t)w * 768 + q * 24);
    const uint4* op = (const uint4*)o;
    dp[0] = op[0]; dp[1] = op[1]; dp[2] = op[2];
}

// ==================== mma.sync bf16 GEMM v2 (ldmatrix + swizzle) ====================
// C[M,N] = A[M,K] @ B[N,K]^T (+bias[n]) (+addrows[addidx[m*stride]][n])
// CTA 128x128, K-tile 64, 8 warps (2x4), warp tile 64x32, 2-stage cp.async.
// smem tile: rows of 64 bf16 (128B); 16B chunk swizzle: chunk' = ck ^ (row&7).
#define KT 64

__device__ __forceinline__ void mma16816(float* d, const uint32_t* a, const uint32_t* b) {
    asm volatile(
        "mma.sync.aligned.m16n8k16.row.col.f32.bf16.bf16.f32 "
        "{%0,%1,%2,%3}, {%4,%5,%6,%7}, {%8,%9}, {%0,%1,%2,%3};"
        : "+f"(d[0]), "+f"(d[1]), "+f"(d[2]), "+f"(d[3])
        : "r"(a[0]), "r"(a[1]), "r"(a[2]), "r"(a[3]), "r"(b[0]), "r"(b[1]));
}

// 2048 16B chunks per stage (A 128x64 + B 128x64 bf16), 256 threads x 8
#define STAGE_LOAD(s, kt) do {                                                     \
    _Pragma("unroll")                                                              \
    for (int j_ = 0; j_ < 8; j_++) {                                               \
        int ch_ = tid + j_ * 256;                                                  \
        int isB_ = ch_ >> 10, c2_ = ch_ & 1023;                                    \
        int row_ = c2_ >> 3, ck_ = c2_ & 7;                                        \
        const __nv_bfloat16* gp_ = (isB_ ? B + (size_t)(n0 + row_) * K             \
                                         : A + (size_t)(m0 + row_) * K)            \
                                   + (kt) + ck_ * 8;                               \
        uint32_t sp_ = sbase + (s) * 32768 + isB_ * 16384                          \
                     + row_ * 128 + ((ck_ ^ (row_ & 7)) * 16);                     \
        asm volatile("cp.async.cg.shared.global [%0], [%1], 16;"                   \
                     :: "r"(sp_), "l"(gp_));                                       \
    }                                                                              \
    asm volatile("cp.async.commit_group;");                                        \
} while (0)

__global__ __launch_bounds__(256, 2)
void mma_gemm_kernel(const __nv_bfloat16* __restrict__ A,
                     const __nv_bfloat16* __restrict__ B,
                     float* __restrict__ C, int M, int N, int K,
                     const float* __restrict__ bias,
                     const float* __restrict__ addrows,
                     const int* __restrict__ addidx, int idx_stride) {
    extern __shared__ char smraw[];
    uint32_t sb;
    asm("{ .reg .u64 t; cvta.to.shared.u64 t, %1; cvt.u32.u64 %0, t; }"
        : "=r"(sb) : "l"(smraw));
    const uint32_t sbase = (sb + 1023u) & ~1023u;
    const int tid = threadIdx.x;
    const int lane = tid & 31, wid = tid >> 5;
    const int wm = wid >> 2, wn = wid & 3;       // 2 x 4 warp grid
    const int m0 = blockIdx.y * 128, n0 = blockIdx.x * 128;
    const int lrow = lane & 7;                   // swizzle row bits
    const int half8 = ((lane >> 3) & 1);         // +8 row (A) / +k8 (B)
    const int khalf = (lane >> 4);               // +k8 (A) / +8 row (B)

    float acc[4][4][4];
    #pragma unroll
    for (int i = 0; i < 4; i++)
        #pragma unroll
        for (int j = 0; j < 4; j++)
            #pragma unroll
            for (int q = 0; q < 4; q++) acc[i][j][q] = 0.f;

    STAGE_LOAD(0, 0);
    const int nk = K / KT;
    for (int kt = 0; kt < nk; kt++) {
        if (kt + 1 < nk) {
            STAGE_LOAD((kt + 1) & 1, (kt + 1) * KT);
            asm volatile("cp.async.wait_group 1;");
        } else {
            asm volatile("cp.async.wait_group 0;");
        }
        __syncthreads();

        const uint32_t Abase = sbase + (kt & 1) * 32768;
        const uint32_t Bbase = Abase + 16384;
        #pragma unroll
        for (int k16 = 0; k16 < KT; k16 += 16) {
            const int k8 = k16 >> 3;
            uint32_t a[4][4], b[2][4];
            #pragma unroll
            for (int mi = 0; mi < 4; mi++) {
                int row = wm * 64 + mi * 16 + lrow + half8 * 8;
                uint32_t ad = Abase + row * 128 + (((k8 + khalf) ^ lrow) * 16);
                asm volatile(
                    "ldmatrix.sync.aligned.m8n8.x4.shared.b16 {%0,%1,%2,%3}, [%4];"
                    : "=r"(a[mi][0]), "=r"(a[mi][1]), "=r"(a[mi][2]), "=r"(a[mi][3])
                    : "r"(ad));
            }
            #pragma unroll
            for (int p = 0; p < 2; p++) {
                int nrow = wn * 32 + p * 16 + khalf * 8 + lrow;
                uint32_t bd = Bbase + nrow * 128 + (((k8 + half8) ^ lrow) * 16);
                asm volatile(
                    "ldmatrix.sync.aligned.m8n8.x4.shared.b16 {%0,%1,%2,%3}, [%4];"
                    : "=r"(b[p][0]), "=r"(b[p][1]), "=r"(b[p][2]), "=r"(b[p][3])
                    : "r"(bd));
            }
            #pragma unroll
            for (int mi = 0; mi < 4; mi++)
                #pragma unroll
                for (int p = 0; p < 2; p++) {
                    mma16816(acc[mi][p * 2],     a[mi], &b[p][0]);
                    mma16816(acc[mi][p * 2 + 1], a[mi], &b[p][2]);
                }
        }
        __syncthreads();
    }

    // epilogue: thread holds C rows (.. + r, +8), cols (.. + cp2, +1)
    const int r = lane >> 2, cp2 = (lane & 3) * 2;
    #pragma unroll
    for (int mi = 0; mi < 4; mi++) {
        int row0 = m0 + wm * 64 + mi * 16 + r;
        int row1 = row0 + 8;
        const float* ar0 = nullptr;
        const float* ar1 = nullptr;
        if (addrows) {
            ar0 = addrows + (size_t)addidx[(size_t)row0 * idx_stride] * N;
            ar1 = addrows + (size_t)addidx[(size_t)row1 * idx_stride] * N;
        }
        #pragma unroll
        for (int nj = 0; nj < 4; nj++) {
            int col = n0 + wn * 32 + nj * 8 + cp2;
            float v0 = acc[mi][nj][0], v1 = acc[mi][nj][1];
            float v2 = acc[mi][nj][2], v3 = acc[mi][nj][3];
            if (bias) {
                float2 b2 = *(const float2*)(bias + col);
                v0 += b2.x; v1 += b2.y; v2 += b2.x; v3 += b2.y;
            }
            if (ar0) {
                float2 a0 = *(const float2*)(ar0 + col);
                float2 a1 = *(const float2*)(ar1 + col);
                v0 += a0.x; v1 += a0.y; v2 += a1.x; v3 += a1.y;
            }
            *(float2*)(C + (size_t)row0 * N + col) = make_float2(v0, v1);
            *(float2*)(C + (size_t)row1 * N + col) = make_float2(v2, v3);
        }
    }
}
#define GEMM_SMEM (1024 + 2 * 32768)

// ---------------- gather word-LSTM input -> triple bf16 directly ----------------
__global__ void gather_xw3_kernel(const int* __restrict__ word_idx,
                                  const float* __restrict__ word_emb) {
    int idx = blockIdx.x * blockDim.x + threadIdx.x;   // NBS*64, 8 elems each
    int w = idx >> 6, q = idx & 63;
    const float* src = (q < 32)
        ? word_emb + (size_t)word_idx[w] * NE + q * 8
        : g_hc + (size_t)w * NE + (q - 32) * 8;
    float4 s0 = *(const float4*)(src);
    float4 s1 = *(const float4*)(src + 4);
    float v[8] = {s0.x, s0.y, s0.z, s0.w, s1.x, s1.y, s1.z, s1.w};
    unsigned short o[24];
    #pragma unroll
    for (int j = 0; j < 8; j++) {
        __nv_bfloat16 hi = __float2bfloat16(v[j]);
        __nv_bfloat16 lo = __float2bfloat16(v[j] - __bfloat162float(hi));
        o[3*j] = __bfloat16_as_ushort(hi);
        o[3*j+1] = __bfloat16_as_ushort(lo);
        o[3*j+2] = __bfloat16_as_ushort(hi);
    }
    uint4* dp = (uint4*)(g_xw3 + (size_t)w * 1536 + q * 24);
    const uint4* op = (const uint4*)o;
    dp[0] = op[0]; dp[1] = op[1]; dp[2] = op[2];
}

// ---------------- persistent word LSTM: 1024 steps, grid barrier ----------------
__global__ void word_lstm_kernel(const float* __restrict__ Whh) {
    extern __shared__ float sm[];
    float* w_s = sm;              // [16][512]
    float* h_s = sm + 16 * 512;   // [32][516]
    const int tid = threadIdx.x;
    const int b = tid >> 2, ul = tid & 3;
    const int u = blockIdx.x * 4 + ul;

    for (int i = tid; i < 16 * 512; i += 128) {
        int rr = i >> 9, k = i & 511;
        int grow = (rr >> 2) * NH + blockIdx.x * 4 + (rr & 3);
        w_s[i] = Whh[(size_t)grow * NH + k];
    }

    const float* wp0 = w_s + (0 + ul) * 512;
    const float* wp1 = w_s + (4 + ul) * 512;
    const float* wp2 = w_s + (8 + ul) * 512;
    const float* wp3 = w_s + (12 + ul) * 512;

    float c = 0.f;
    unsigned target = 0;
    for (int t = 0; t < NS; ++t) {
        if (t == 0) {
            for (int i = tid; i < 32 * 128; i += 128) {
                int bb = i >> 7, kq = i & 127;
                *(float4*)(h_s + bb * 516 + kq * 4) = make_float4(0, 0, 0, 0);
            }
        } else {
            const float* hp = g_whs + (size_t)(t - 1) * NB * NH;
            for (int i = tid; i < 32 * 128; i += 128) {
                int bb = i >> 7, kq = i & 127;
                *(float4*)(h_s + bb * 516 + kq * 4) = *(const float4*)(hp + bb * 512 + kq * 4);
            }
        }
        __syncthreads();

        float a0 = 0.f, a1 = 0.f, a2 = 0.f, a3 = 0.f;
        const float* hr = h_s + b * 516;
        #pragma unroll 4
        for (int k = 0; k < 512; k += 4) {
            float4 hv = *(const float4*)(hr + k);
            float4 w0 = *(const float4*)(wp0 + k);
            float4 w1 = *(const float4*)(wp1 + k);
            float4 w2 = *(const float4*)(wp2 + k);
            float4 w3 = *(const float4*)(wp3 + k);
            a0 += hv.x * w0.x + hv.y * w0.y + hv.z * w0.z + hv.w * w0.w;
            a1 += hv.x * w1.x + hv.y * w1.y + hv.z * w1.z + hv.w * w1.w;
            a2 += hv.x * w2.x + hv.y * w2.y + hv.z * w2.z + hv.w * w2.w;
            a3 += hv.x * w3.x + hv.y * w3.y + hv.z * w3.z + hv.w * w3.w;
        }

        const float* gin = g_gin + ((size_t)b * NS + t) * (4 * NH);
        float iv = sigm(a0 + gin[u]);
        float fv = sigm(a1 + gin[NH + u]);
        float gv = tanhf(a2 + gin[2 * NH + u]);
        float ov = sigm(a3 + gin[3 * NH + u]);
        c = fv * c + iv * gv;
        float h = ov * tanhf(c);
        g_whs[(size_t)t * NB * NH + b * NH + u] = h;

        __syncthreads();
        target += gridDim.x;
        if (tid == 0) {
            __threadfence();
            atomicAdd(&g_bar, 1u);
            while (*((volatile unsigned int*)&g_bar) < target) { }
            __threadfence();
        }
        __syncthreads();
    }
}

// ---------------- tag projection + log_softmax ----------------
__global__ void tag_kernel(const float* __restrict__ Wt, const float* __restrict__ bt,
                           float* __restrict__ out) {
    __shared__ float hs[8][512];
    __shared__ float lg[8][52];
    int tid = threadIdx.x, warp = tid >> 5, lane = tid & 31;
    int wbase = blockIdx.x * 8;

    for (int i = tid; i < 8 * 512; i += 256) {
        int tok = i >> 9, k = i & 511;
        int w = wbase + tok;
        int b = w >> 10, s = w & 1023;
        hs[tok][k] = g_whs[((size_t)s * NB + b) * NH + k];
    }
    __syncthreads();

    for (int tg = 0; tg < NT; ++tg) {
        const float* wr = Wt + (size_t)tg * NH;
        float p = 0.f;
        for (int k = lane; k < NH; k += 32) p += hs[warp][k] * wr[k];
        #pragma unroll
        for (int o = 16; o; o >>= 1) p += __shfl_xor_sync(0xffffffff, p, o);
        if (lane == 0) lg[warp][tg] = p + bt[tg];
    }
    __syncwarp();

    float v0 = (lane < NT) ? lg[warp][lane] : -1e30f;
    float v1 = (lane + 32 < NT) ? lg[warp][lane + 32] : -1e30f;
    float m = fmaxf(v0, v1);
    #pragma unroll
    for (int o = 16; o; o >>= 1) m = fmaxf(m, __shfl_xor_sync(0xffffffff, m, o));
    float e = ((lane < NT) ? expf(v0 - m) : 0.f) + ((lane + 32 < NT) ? expf(v1 - m) : 0.f);
    #pragma unroll
    for (int o = 16; o; o >>= 1) e += __shfl_xor_sync(0xffffffff, e, o);
    float lse = m + logf(e);

    int w = wbase + warp;
    if (lane < NT)      out[(size_t)w * NT + lane]      = v0 - lse;
    if (lane + 32 < NT) out[(size_t)w * NT + lane + 32] = v1 - lse;
}

// ---------------- host entry ----------------
extern "C" void kernel_launch(void* const* d_in, const int* in_sizes, int n_in,
                              void* d_out, int out_size) {
    const int*   char_idx = (const int*)d_in[0];
    const int*   word_idx = (const int*)d_in[1];
    const float* char_emb = (const float*)d_in[2];
    const float* word_emb = (const float*)d_in[3];
    const float* Wc_ih    = (const float*)d_in[4];
    const float* Wc_hh    = (const float*)d_in[5];
    const float* bc       = (const float*)d_in[6];
    const float* Ww_ih    = (const float*)d_in[7];
    const float* Ww_hh    = (const float*)d_in[8];
    const float* bw       = (const float*)d_in[9];
    const float* Wt       = (const float*)d_in[10];
    const float* bt       = (const float*)d_in[11];
    float* out = (float*)d_out;

    float *p_gates, *p_gin, *p_cproj;
    __nv_bfloat16 *p_h3, *p_wchh3, *p_xw3, *p_wwih3;
    cudaGetSymbolAddress((void**)&p_gates, g_gates);
    cudaGetSymbolAddress((void**)&p_gin,   g_gin);
    cudaGetSymbolAddress((void**)&p_cproj, g_cproj);
    cudaGetSymbolAddress((void**)&p_h3,    g_h3);
    cudaGetSymbolAddress((void**)&p_wchh3, g_wchh3);
    cudaGetSymbolAddress((void**)&p_xw3,   g_xw3);
    cudaGetSymbolAddress((void**)&p_wwih3, g_wwih3);

    cudaFuncSetAttribute(mma_gemm_kernel,
                         cudaFuncAttributeMaxDynamicSharedMemorySize, GEMM_SMEM);
    cudaFuncSetAttribute(word_lstm_kernel,
                         cudaFuncAttributeMaxDynamicSharedMemorySize, 98816);

    // launch order aims the ncu capture slot (#6) at the first char GEMM
    init_kernel<<<8192, 256>>>();                                            // 1
    cproj_kernel<<<128, 256>>>(char_emb, Wc_ih, bc);                         // 2
    convert3_kernel<<<(4*NE*NE/8 + 255)/256, 256>>>(Wc_hh, p_wchh3,
                                                    4*NE*NE/8, 1);           // 3
    gather_gates0_kernel<<<NBS, 256>>>(char_idx);                            // 4
    char_cell_kernel<<<NBS*32/256, 256>>>();                                 // 5
    for (int t = 1; t < NC; t++) {
        mma_gemm_kernel<<<dim3(1024/128, NBS/128), 256, GEMM_SMEM>>>(        // 6 = first
            p_h3, p_wchh3, p_gates, NBS, 1024, 3*NE,
            nullptr, p_cproj, char_idx + t, NC);
        char_cell_kernel<<<NBS*32/256, 256>>>();
    }

    // word input projection
    convert3_kernel<<<(4*NH*2*NE/8 + 255)/256, 256>>>(Ww_ih, p_wwih3,
                                                      4*NH*2*NE/8, 1);
    gather_xw3_kernel<<<NBS*64/256, 256>>>(word_idx, word_emb);
    mma_gemm_kernel<<<dim3(2048/128, NBS/128), 256, GEMM_SMEM>>>(
        p_xw3, p_wwih3, p_gin, NBS, 2048, 3*2*NE,
        bw, nullptr, nullptr, 0);

    // persistent word LSTM (1024 steps, internal grid barrier)
    word_lstm_kernel<<<128, 128, 98816>>>(Ww_hh);

    // tag projection + log_softmax
    tag_kernel<<<NBS/8, 256>>>(Wt, bt, out);
}

// round 14
// speedup vs baseline: 1.6139x; 1.4169x over previous
#include <cuda_runtime.h>
#include <cuda_bf16.h>
#include <cstdint>
#include <math.h>

// Problem constants
#define NB 32
#define NS 1024
#define NC 12
#define NE 256
#define NH 512
#define NT 50
#define NBS (NB*NS)      // 32768 words

// ---------------- device scratch (no cudaMalloc allowed) ----------------
__device__ float g_cproj[128 * 4 * NE];              // [128][1024] char input proj (+bc)
__device__ float g_cc[NBS * NE];                     // char LSTM c
__device__ float g_gates[NBS * 4 * NE];              // char gates scratch
__device__ __nv_bfloat16 g_h3[NBS * 3 * NE];         // h triple bf16 [hi,lo,hi]
__device__ __nv_bfloat16 g_wchh3[4 * NE * 3 * NE];   // Wc_hh triple [hi,hi,lo]
__device__ __nv_bfloat16 g_xw3[NBS * 3 * 2 * NE];    // [we;char_feat] triple [hi,lo,hi]
__device__ __nv_bfloat16 g_wwih3[4 * NH * 3 * 2 * NE]; // Ww_ih triple [hi,hi,lo]
__device__ float g_gin[NBS * 4 * NH];                // word input projection
__device__ float g_whs[NS * NB * NH];                // word hidden trace [t][b][h]
__device__ unsigned int g_bar;                       // grid barrier arrival counter
__device__ unsigned int g_flag;                      // grid barrier release flag

__device__ __forceinline__ float sigm(float x) { return 1.0f / (1.0f + expf(-x)); }

// B-side triple conversion body: [hi, hi, lo] per element, 8 elems per idx
__device__ __forceinline__ void conv3_body(const float* __restrict__ src,
                                           __nv_bfloat16* __restrict__ dst, int idx) {
    float4 s0 = ((const float4*)src)[idx * 2];
    float4 s1 = ((const float4*)src)[idx * 2 + 1];
    float v[8] = {s0.x, s0.y, s0.z, s0.w, s1.x, s1.y, s1.z, s1.w};
    unsigned short o[24];
    #pragma unroll
    for (int j = 0; j < 8; j++) {
        __nv_bfloat16 hi = __float2bfloat16(v[j]);
        __nv_bfloat16 lo = __float2bfloat16(v[j] - __bfloat162float(hi));
        o[3*j] = __bfloat16_as_ushort(hi);
        o[3*j+1] = __bfloat16_as_ushort(hi);
        o[3*j+2] = __bfloat16_as_ushort(lo);
    }
    uint4* dp = (uint4*)(dst + (size_t)idx * 24);
    const uint4* op = (const uint4*)o;
    dp[0] = op[0]; dp[1] = op[1]; dp[2] = op[2];
}

// ---------------- fused prep: zero cc + barrier reset + cproj + weight conversions ----------------
// blocks [0,8192): zero g_cc (+bar reset)   [8192,8320): cproj
// [8320,8448): conv3 Wc_hh                  [8448,8960): conv3 Ww_ih
__global__ void prep_kernel(const float* __restrict__ char_emb,
                            const float* __restrict__ Wc_ih,
                            const float* __restrict__ bc,
                            const float* __restrict__ Wc_hh,
                            const float* __restrict__ Ww_ih) {
    __shared__ float ce[NE];
    int blk = blockIdx.x, tid = threadIdx.x;
    if (blk < 8192) {
        int idx = blk * 256 + tid;
        ((float4*)g_cc)[idx] = make_float4(0.f, 0.f, 0.f, 0.f);
        if (idx == 0) { g_bar = 0u; g_flag = 0u; }
    } else if (blk < 8320) {
        int c = blk - 8192;
        for (int i = tid; i < NE; i += 256) ce[i] = char_emb[c * NE + i];
        __syncthreads();
        for (int n = tid; n < 4 * NE; n += 256) {
            const float* wr = Wc_ih + (size_t)n * NE;
            float acc = bc[n];
            #pragma unroll 4
            for (int k = 0; k < NE; k++) acc += ce[k] * wr[k];
            g_cproj[c * 4 * NE + n] = acc;
        }
    } else if (blk < 8448) {
        int idx = (blk - 8320) * 256 + tid;           // n8 = 4*NE*NE/8 = 32768
        conv3_body(Wc_hh, g_wchh3, idx);
    } else {
        int idx = (blk - 8448) * 256 + tid;           // n8 = 4*NH*2*NE/8 = 131072
        conv3_body(Ww_ih, g_wwih3, idx);
    }
}

// ---------------- t=0 char gates: pure gather (h=0) ----------------
__global__ void gather_gates0_kernel(const int* __restrict__ char_idx) {
    int idx = blockIdx.x * blockDim.x + threadIdx.x;   // over NBS*256 float4
    int w = idx >> 8, q = idx & 255;
    int ci = char_idx[w * NC];
    ((float4*)g_gates)[(size_t)w * 256 + q] = ((const float4*)g_cproj)[(size_t)ci * 256 + q];
}

// ---------------- char LSTM cell update + triple-bf16 h emit ----------------
__global__ void char_cell_kernel() {
    int idx = blockIdx.x * blockDim.x + threadIdx.x;   // NBS*32 threads, 8 units each
    int w = idx >> 5, q = idx & 31;
    const float* gp = g_gates + (size_t)w * 1024 + q * 8;
    float4 i0 = *(const float4*)(gp);        float4 i1 = *(const float4*)(gp + 4);
    float4 f0 = *(const float4*)(gp + 256);  float4 f1 = *(const float4*)(gp + 260);
    float4 g0 = *(const float4*)(gp + 512);  float4 g1 = *(const float4*)(gp + 516);
    float4 o0 = *(const float4*)(gp + 768);  float4 o1 = *(const float4*)(gp + 772);
    float* cp = g_cc + (size_t)w * 256 + q * 8;
    float4 c0 = *(const float4*)(cp);        float4 c1 = *(const float4*)(cp + 4);
    float gi[8] = {i0.x,i0.y,i0.z,i0.w,i1.x,i1.y,i1.z,i1.w};
    float gf[8] = {f0.x,f0.y,f0.z,f0.w,f1.x,f1.y,f1.z,f1.w};
    float gg[8] = {g0.x,g0.y,g0.z,g0.w,g1.x,g1.y,g1.z,g1.w};
    float go[8] = {o0.x,o0.y,o0.z,o0.w,o1.x,o1.y,o1.z,o1.w};
    float cc[8] = {c0.x,c0.y,c0.z,c0.w,c1.x,c1.y,c1.z,c1.w};
    float h[8];
    #pragma unroll
    for (int j = 0; j < 8; j++) {
        cc[j] = sigm(gf[j]) * cc[j] + sigm(gi[j]) * tanhf(gg[j]);
        h[j] = sigm(go[j]) * tanhf(cc[j]);
    }
    *(float4*)(cp)     = make_float4(cc[0],cc[1],cc[2],cc[3]);
    *(float4*)(cp + 4) = make_float4(cc[4],cc[5],cc[6],cc[7]);
    unsigned short o[24];
    #pragma unroll
    for (int j = 0; j < 8; j++) {
        __nv_bfloat16 hi = __float2bfloat16(h[j]);
        __nv_bfloat16 lo = __float2bfloat16(h[j] - __bfloat162float(hi));
        o[3*j] = __bfloat16_as_ushort(hi);
        o[3*j+1] = __bfloat16_as_ushort(lo);
        o[3*j+2] = __bfloat16_as_ushort(hi);
    }
    uint4* dp = (uint4*)(g_h3 + (size_t)w * 768 + q * 24);
    const uint4* op = (const uint4*)o;
    dp[0] = op[0]; dp[1] = op[1]; dp[2] = op[2];
}

// ==================== mma.sync bf16 GEMM (ldmatrix + swizzle) ====================
// C[M,N] = A[M,K] @ B[N,K]^T (+bias[n]) (+addrows[addidx[m*stride]][n])
// CTA 128x128, K-tile 64, 8 warps (2x4), warp tile 64x32, 2-stage cp.async.
#define KT 64

__device__ __forceinline__ void mma16816(float* d, const uint32_t* a, const uint32_t* b) {
    asm volatile(
        "mma.sync.aligned.m16n8k16.row.col.f32.bf16.bf16.f32 "
        "{%0,%1,%2,%3}, {%4,%5,%6,%7}, {%8,%9}, {%0,%1,%2,%3};"
        : "+f"(d[0]), "+f"(d[1]), "+f"(d[2]), "+f"(d[3])
        : "r"(a[0]), "r"(a[1]), "r"(a[2]), "r"(a[3]), "r"(b[0]), "r"(b[1]));
}

#define STAGE_LOAD(s, kt) do {                                                     \
    _Pragma("unroll")                                                              \
    for (int j_ = 0; j_ < 8; j_++) {                                               \
        int ch_ = tid + j_ * 256;                                                  \
        int isB_ = ch_ >> 10, c2_ = ch_ & 1023;                                    \
        int row_ = c2_ >> 3, ck_ = c2_ & 7;                                        \
        const __nv_bfloat16* gp_ = (isB_ ? B + (size_t)(n0 + row_) * K             \
                                         : A + (size_t)(m0 + row_) * K)            \
                                   + (kt) + ck_ * 8;                               \
        uint32_t sp_ = sbase + (s) * 32768 + isB_ * 16384                          \
                     + row_ * 128 + ((ck_ ^ (row_ & 7)) * 16);                     \
        asm volatile("cp.async.cg.shared.global [%0], [%1], 16;"                   \
                     :: "r"(sp_), "l"(gp_));                                       \
    }                                                                              \
    asm volatile("cp.async.commit_group;");                                        \
} while (0)

__global__ __launch_bounds__(256, 2)
void mma_gemm_kernel(const __nv_bfloat16* __restrict__ A,
                     const __nv_bfloat16* __restrict__ B,
                     float* __restrict__ C, int M, int N, int K,
                     const float* __restrict__ bias,
                     const float* __restrict__ addrows,
                     const int* __restrict__ addidx, int idx_stride) {
    extern __shared__ char smraw[];
    uint32_t sb;
    asm("{ .reg .u64 t; cvta.to.shared.u64 t, %1; cvt.u32.u64 %0, t; }"
        : "=r"(sb) : "l"(smraw));
    const uint32_t sbase = (sb + 1023u) & ~1023u;
    const int tid = threadIdx.x;
    const int lane = tid & 31, wid = tid >> 5;
    const int wm = wid >> 2, wn = wid & 3;       // 2 x 4 warp grid
    const int m0 = blockIdx.y * 128, n0 = blockIdx.x * 128;
    const int lrow = lane & 7;
    const int half8 = ((lane >> 3) & 1);
    const int khalf = (lane >> 4);

    float acc[4][4][4];
    #pragma unroll
    for (int i = 0; i < 4; i++)
        #pragma unroll
        for (int j = 0; j < 4; j++)
            #pragma unroll
            for (int q = 0; q < 4; q++) acc[i][j][q] = 0.f;

    STAGE_LOAD(0, 0);
    const int nk = K / KT;
    for (int kt = 0; kt < nk; kt++) {
        if (kt + 1 < nk) {
            STAGE_LOAD((kt + 1) & 1, (kt + 1) * KT);
            asm volatile("cp.async.wait_group 1;");
        } else {
            asm volatile("cp.async.wait_group 0;");
        }
        __syncthreads();

        const uint32_t Abase = sbase + (kt & 1) * 32768;
        const uint32_t Bbase = Abase + 16384;
        #pragma unroll
        for (int k16 = 0; k16 < KT; k16 += 16) {
            const int k8 = k16 >> 3;
            uint32_t a[4][4], b[2][4];
            #pragma unroll
            for (int mi = 0; mi < 4; mi++) {
                int row = wm * 64 + mi * 16 + lrow + half8 * 8;
                uint32_t ad = Abase + row * 128 + (((k8 + khalf) ^ lrow) * 16);
                asm volatile(
                    "ldmatrix.sync.aligned.m8n8.x4.shared.b16 {%0,%1,%2,%3}, [%4];"
                    : "=r"(a[mi][0]), "=r"(a[mi][1]), "=r"(a[mi][2]), "=r"(a[mi][3])
                    : "r"(ad));
            }
            #pragma unroll
            for (int p = 0; p < 2; p++) {
                int nrow = wn * 32 + p * 16 + khalf * 8 + lrow;
                uint32_t bd = Bbase + nrow * 128 + (((k8 + half8) ^ lrow) * 16);
                asm volatile(
                    "ldmatrix.sync.aligned.m8n8.x4.shared.b16 {%0,%1,%2,%3}, [%4];"
                    : "=r"(b[p][0]), "=r"(b[p][1]), "=r"(b[p][2]), "=r"(b[p][3])
                    : "r"(bd));
            }
            #pragma unroll
            for (int mi = 0; mi < 4; mi++)
                #pragma unroll
                for (int p = 0; p < 2; p++) {
                    mma16816(acc[mi][p * 2],     a[mi], &b[p][0]);
                    mma16816(acc[mi][p * 2 + 1], a[mi], &b[p][2]);
                }
        }
        __syncthreads();
    }

    const int r = lane >> 2, cp2 = (lane & 3) * 2;
    #pragma unroll
    for (int mi = 0; mi < 4; mi++) {
        int row0 = m0 + wm * 64 + mi * 16 + r;
        int row1 = row0 + 8;
        const float* ar0 = nullptr;
        const float* ar1 = nullptr;
        if (addrows) {
            ar0 = addrows + (size_t)addidx[(size_t)row0 * idx_stride] * N;
            ar1 = addrows + (size_t)addidx[(size_t)row1 * idx_stride] * N;
        }
        #pragma unroll
        for (int nj = 0; nj < 4; nj++) {
            int col = n0 + wn * 32 + nj * 8 + cp2;
            float v0 = acc[mi][nj][0], v1 = acc[mi][nj][1];
            float v2 = acc[mi][nj][2], v3 = acc[mi][nj][3];
            if (bias) {
                float2 b2 = *(const float2*)(bias + col);
                v0 += b2.x; v1 += b2.y; v2 += b2.x; v3 += b2.y;
            }
            if (ar0) {
                float2 a0 = *(const float2*)(ar0 + col);
                float2 a1 = *(const float2*)(ar1 + col);
                v0 += a0.x; v1 += a0.y; v2 += a1.x; v3 += a1.y;
            }
            *(float2*)(C + (size_t)row0 * N + col) = make_float2(v0, v1);
            *(float2*)(C + (size_t)row1 * N + col) = make_float2(v2, v3);
        }
    }
}
#define GEMM_SMEM (1024 + 2 * 32768)

// ---------------- gather word-LSTM input -> triple bf16 (h part copied from g_h3) ----------------
__global__ void gather_xw3_kernel(const int* __restrict__ word_idx,
                                  const float* __restrict__ word_emb) {
    int idx = blockIdx.x * blockDim.x + threadIdx.x;   // NBS*64, 8 elems each
    int w = idx >> 6, q = idx & 63;
    uint4* dp = (uint4*)(g_xw3 + (size_t)w * 1536 + q * 24);
    if (q < 32) {
        const float* src = word_emb + (size_t)word_idx[w] * NE + q * 8;
        float4 s0 = *(const float4*)(src);
        float4 s1 = *(const float4*)(src + 4);
        float v[8] = {s0.x, s0.y, s0.z, s0.w, s1.x, s1.y, s1.z, s1.w};
        unsigned short o[24];
        #pragma unroll
        for (int j = 0; j < 8; j++) {
            __nv_bfloat16 hi = __float2bfloat16(v[j]);
            __nv_bfloat16 lo = __float2bfloat16(v[j] - __bfloat162float(hi));
            o[3*j] = __bfloat16_as_ushort(hi);
            o[3*j+1] = __bfloat16_as_ushort(lo);
            o[3*j+2] = __bfloat16_as_ushort(hi);
        }
        const uint4* op = (const uint4*)o;
        dp[0] = op[0]; dp[1] = op[1]; dp[2] = op[2];
    } else {
        const uint4* sp = (const uint4*)(g_h3 + (size_t)w * 768 + (q - 32) * 24);
        dp[0] = sp[0]; dp[1] = sp[1]; dp[2] = sp[2];
    }
}

// ---------------- persistent word LSTM: 1024 steps, split-flag grid barrier ----------------
// weight smem stride 520 (banks 0/8/16/24 per ul -> conflict-free)
#define WSTR 520
__global__ void word_lstm_kernel(const float* __restrict__ Whh) {
    extern __shared__ float sm[];
    float* w_s = sm;                 // [16][WSTR]
    float* h_s = sm + 16 * WSTR;     // [32][516]
    const int tid = threadIdx.x;
    const int b = tid >> 2, ul = tid & 3;
    const int u = blockIdx.x * 4 + ul;

    for (int i = tid; i < 16 * 512; i += 128) {
        int rr = i >> 9, k = i & 511;
        int grow = (rr >> 2) * NH + blockIdx.x * 4 + (rr & 3);
        w_s[rr * WSTR + k] = Whh[(size_t)grow * NH + k];
    }

    const float* wp0 = w_s + (0 + ul) * WSTR;
    const float* wp1 = w_s + (4 + ul) * WSTR;
    const float* wp2 = w_s + (8 + ul) * WSTR;
    const float* wp3 = w_s + (12 + ul) * WSTR;

    float c = 0.f;
    unsigned tgt = 0;
    for (int t = 0; t < NS; ++t) {
        if (t == 0) {
            for (int i = tid; i < 32 * 128; i += 128) {
                int bb = i >> 7, kq = i & 127;
                *(float4*)(h_s + bb * 516 + kq * 4) = make_float4(0, 0, 0, 0);
            }
        } else {
            const float* hp = g_whs + (size_t)(t - 1) * NB * NH;
            for (int i = tid; i < 32 * 128; i += 128) {
                int bb = i >> 7, kq = i & 127;
                *(float4*)(h_s + bb * 516 + kq * 4) = *(const float4*)(hp + bb * 512 + kq * 4);
            }
        }
        __syncthreads();

        float a0 = 0.f, a1 = 0.f, a2 = 0.f, a3 = 0.f;
        const float* hr = h_s + b * 516;
        #pragma unroll 4
        for (int k = 0; k < 512; k += 4) {
            float4 hv = *(const float4*)(hr + k);
            float4 w0 = *(const float4*)(wp0 + k);
            float4 w1 = *(const float4*)(wp1 + k);
            float4 w2 = *(const float4*)(wp2 + k);
            float4 w3 = *(const float4*)(wp3 + k);
            a0 += hv.x * w0.x + hv.y * w0.y + hv.z * w0.z + hv.w * w0.w;
            a1 += hv.x * w1.x + hv.y * w1.y + hv.z * w1.z + hv.w * w1.w;
            a2 += hv.x * w2.x + hv.y * w2.y + hv.z * w2.z + hv.w * w2.w;
            a3 += hv.x * w3.x + hv.y * w3.y + hv.z * w3.z + hv.w * w3.w;
        }

        const float* gin = g_gin + ((size_t)b * NS + t) * (4 * NH);
        float iv = sigm(a0 + gin[u]);
        float fv = sigm(a1 + gin[NH + u]);
        float gv = tanhf(a2 + gin[2 * NH + u]);
        float ov = sigm(a3 + gin[3 * NH + u]);
        c = fv * c + iv * gv;
        float h = ov * tanhf(c);
        g_whs[(size_t)t * NB * NH + b * NH + u] = h;

        __syncthreads();
        tgt += 128;
        if (tid == 0) {
            __threadfence();
            unsigned old = atomicAdd(&g_bar, 1u);
            if (old == tgt - 1) {
                *((volatile unsigned int*)&g_flag) = (unsigned)(t + 1);
                __threadfence();
            } else {
                while (*((volatile unsigned int*)&g_flag) < (unsigned)(t + 1)) { }
            }
            __threadfence();
        }
        __syncthreads();
    }
}
#define LSTM_SMEM ((16 * WSTR + 32 * 516) * 4)

// ---------------- tag projection + log_softmax ----------------
__global__ void tag_kernel(const float* __restrict__ Wt, const float* __restrict__ bt,
                           float* __restrict__ out) {
    __shared__ float hs[8][512];
    __shared__ float lg[8][52];
    int tid = threadIdx.x, warp = tid >> 5, lane = tid & 31;
    int wbase = blockIdx.x * 8;

    for (int i = tid; i < 8 * 512; i += 256) {
        int tok = i >> 9, k = i & 511;
        int w = wbase + tok;
        int b = w >> 10, s = w & 1023;
        hs[tok][k] = g_whs[((size_t)s * NB + b) * NH + k];
    }
    __syncthreads();

    for (int tg = 0; tg < NT; ++tg) {
        const float* wr = Wt + (size_t)tg * NH;
        float p = 0.f;
        for (int k = lane; k < NH; k += 32) p += hs[warp][k] * wr[k];
        #pragma unroll
        for (int o = 16; o; o >>= 1) p += __shfl_xor_sync(0xffffffff, p, o);
        if (lane == 0) lg[warp][tg] = p + bt[tg];
    }
    __syncwarp();

    float v0 = (lane < NT) ? lg[warp][lane] : -1e30f;
    float v1 = (lane + 32 < NT) ? lg[warp][lane + 32] : -1e30f;
    float m = fmaxf(v0, v1);
    #pragma unroll
    for (int o = 16; o; o >>= 1) m = fmaxf(m, __shfl_xor_sync(0xffffffff, m, o));
    float e = ((lane < NT) ? expf(v0 - m) : 0.f) + ((lane + 32 < NT) ? expf(v1 - m) : 0.f);
    #pragma unroll
    for (int o = 16; o; o >>= 1) e += __shfl_xor_sync(0xffffffff, e, o);
    float lse = m + logf(e);

    int w = wbase + warp;
    if (lane < NT)      out[(size_t)w * NT + lane]      = v0 - lse;
    if (lane + 32 < NT) out[(size_t)w * NT + lane + 32] = v1 - lse;
}

// ---------------- host entry ----------------
extern "C" void kernel_launch(void* const* d_in, const int* in_sizes, int n_in,
                              void* d_out, int out_size) {
    const int*   char_idx = (const int*)d_in[0];
    const int*   word_idx = (const int*)d_in[1];
    const float* char_emb = (const float*)d_in[2];
    const float* word_emb = (const float*)d_in[3];
    const float* Wc_ih    = (const float*)d_in[4];
    const float* Wc_hh    = (const float*)d_in[5];
    const float* bc       = (const float*)d_in[6];
    const float* Ww_ih    = (const float*)d_in[7];
    const float* Ww_hh    = (const float*)d_in[8];
    const float* bw       = (const float*)d_in[9];
    const float* Wt       = (const float*)d_in[10];
    const float* bt       = (const float*)d_in[11];
    float* out = (float*)d_out;

    float *p_gates, *p_gin, *p_cproj;
    __nv_bfloat16 *p_h3, *p_wchh3, *p_xw3, *p_wwih3;
    cudaGetSymbolAddress((void**)&p_gates, g_gates);
    cudaGetSymbolAddress((void**)&p_gin,   g_gin);
    cudaGetSymbolAddress((void**)&p_cproj, g_cproj);
    cudaGetSymbolAddress((void**)&p_h3,    g_h3);
    cudaGetSymbolAddress((void**)&p_wchh3, g_wchh3);
    cudaGetSymbolAddress((void**)&p_xw3,   g_xw3);
    cudaGetSymbolAddress((void**)&p_wwih3, g_wwih3);

    cudaFuncSetAttribute(mma_gemm_kernel,
                         cudaFuncAttributeMaxDynamicSharedMemorySize, GEMM_SMEM);
    cudaFuncSetAttribute(word_lstm_kernel,
                         cudaFuncAttributeMaxDynamicSharedMemorySize, LSTM_SMEM);

    // launch #4 = first char GEMM (ncu capture lands on the 4th launch)
    prep_kernel<<<8960, 256>>>(char_emb, Wc_ih, bc, Wc_hh, Ww_ih);           // 1
    gather_gates0_kernel<<<NBS, 256>>>(char_idx);                            // 2
    char_cell_kernel<<<NBS*32/256, 256>>>();                                 // 3
    for (int t = 1; t < NC; t++) {
        mma_gemm_kernel<<<dim3(1024/128, NBS/128), 256, GEMM_SMEM>>>(        // 4 = first
            p_h3, p_wchh3, p_gates, NBS, 1024, 3*NE,
            nullptr, p_cproj, char_idx + t, NC);
        char_cell_kernel<<<NBS*32/256, 256>>>();
    }

    // word input projection
    gather_xw3_kernel<<<NBS*64/256, 256>>>(word_idx, word_emb);
    mma_gemm_kernel<<<dim3(2048/128, NBS/128), 256, GEMM_SMEM>>>(
        p_xw3, p_wwih3, p_gin, NBS, 2048, 3*2*NE,
        bw, nullptr, nullptr, 0);

    // persistent word LSTM (1024 steps, internal grid barrier)
    word_lstm_kernel<<<128, 128, LSTM_SMEM>>>(Ww_hh);

    // tag projection + log_softmax
    tag_kernel<<<NBS/8, 256>>>(Wt, bt, out);
}

// round 15
// speedup vs baseline: 2.3040x; 1.4276x over previous
#include <cuda_runtime.h>
#include <cuda_bf16.h>
#include <cstdint>
#include <math.h>

// Problem constants
#define NB 32
#define NS 1024
#define NC 12
#define NE 256
#define NH 512
#define NT 50
#define NBS (NB*NS)      // 32768 words

// ---------------- device scratch (no cudaMalloc allowed) ----------------
__device__ float g_cproj[128 * 4 * NE];              // [128][1024] char input proj (+bc)
__device__ float g_cc[NBS * NE];                     // char LSTM c
__device__ float g_gates[NBS * 4 * NE];              // char gates scratch
__device__ __nv_bfloat16 g_h3[NBS * 3 * NE];         // h triple bf16 [hi,lo,hi]
__device__ __nv_bfloat16 g_wchh3[4 * NE * 3 * NE];   // Wc_hh triple [hi,hi,lo]
__device__ __nv_bfloat16 g_xw3[NBS * 3 * 2 * NE];    // [we;char_feat] triple [hi,lo,hi]
__device__ __nv_bfloat16 g_wwih3[4 * NH * 3 * 2 * NE]; // Ww_ih triple [hi,hi,lo]
__device__ float g_gin[NBS * 4 * NH];                // word input projection
__device__ float g_whs[NS * NB * NH];                // word hidden trace [t][b][h]
__device__ unsigned int g_bar;                       // grid barrier arrival counter
__device__ unsigned int g_flag;                      // grid barrier release flag

__device__ __forceinline__ float sigm(float x) { return 1.0f / (1.0f + expf(-x)); }

// B-side triple conversion body: [hi, hi, lo] per element, 8 elems per idx
__device__ __forceinline__ void conv3_body(const float* __restrict__ src,
                                           __nv_bfloat16* __restrict__ dst, int idx) {
    float4 s0 = ((const float4*)src)[idx * 2];
    float4 s1 = ((const float4*)src)[idx * 2 + 1];
    float v[8] = {s0.x, s0.y, s0.z, s0.w, s1.x, s1.y, s1.z, s1.w};
    unsigned short o[24];
    #pragma unroll
    for (int j = 0; j < 8; j++) {
        __nv_bfloat16 hi = __float2bfloat16(v[j]);
        __nv_bfloat16 lo = __float2bfloat16(v[j] - __bfloat162float(hi));
        o[3*j] = __bfloat16_as_ushort(hi);
        o[3*j+1] = __bfloat16_as_ushort(hi);
        o[3*j+2] = __bfloat16_as_ushort(lo);
    }
    uint4* dp = (uint4*)(dst + (size_t)idx * 24);
    const uint4* op = (const uint4*)o;
    dp[0] = op[0]; dp[1] = op[1]; dp[2] = op[2];
}

// ---------------- fused prep: zero cc + barrier reset + cproj + weight conversions ----------------
__global__ void prep_kernel(const float* __restrict__ char_emb,
                            const float* __restrict__ Wc_ih,
                            const float* __restrict__ bc,
                            const float* __restrict__ Wc_hh,
                            const float* __restrict__ Ww_ih) {
    __shared__ float ce[NE];
    int blk = blockIdx.x, tid = threadIdx.x;
    if (blk < 8192) {
        int idx = blk * 256 + tid;
        ((float4*)g_cc)[idx] = make_float4(0.f, 0.f, 0.f, 0.f);
        if (idx == 0) { g_bar = 0u; g_flag = 0u; }
    } else if (blk < 8320) {
        int c = blk - 8192;
        for (int i = tid; i < NE; i += 256) ce[i] = char_emb[c * NE + i];
        __syncthreads();
        for (int n = tid; n < 4 * NE; n += 256) {
            const float* wr = Wc_ih + (size_t)n * NE;
            float acc = bc[n];
            #pragma unroll 4
            for (int k = 0; k < NE; k++) acc += ce[k] * wr[k];
            g_cproj[c * 4 * NE + n] = acc;
        }
    } else if (blk < 8448) {
        int idx = (blk - 8320) * 256 + tid;           // n8 = 32768
        conv3_body(Wc_hh, g_wchh3, idx);
    } else {
        int idx = (blk - 8448) * 256 + tid;           // n8 = 131072
        conv3_body(Ww_ih, g_wwih3, idx);
    }
}

// ---------------- t=0 char gates: pure gather (h=0) ----------------
__global__ void gather_gates0_kernel(const int* __restrict__ char_idx) {
    int idx = blockIdx.x * blockDim.x + threadIdx.x;   // over NBS*256 float4
    int w = idx >> 8, q = idx & 255;
    int ci = char_idx[w * NC];
    ((float4*)g_gates)[(size_t)w * 256 + q] = ((const float4*)g_cproj)[(size_t)ci * 256 + q];
}

// ---------------- char LSTM cell update + triple-bf16 h emit ----------------
__global__ void char_cell_kernel() {
    int idx = blockIdx.x * blockDim.x + threadIdx.x;   // NBS*32 threads, 8 units each
    int w = idx >> 5, q = idx & 31;
    const float* gp = g_gates + (size_t)w * 1024 + q * 8;
    float4 i0 = *(const float4*)(gp);        float4 i1 = *(const float4*)(gp + 4);
    float4 f0 = *(const float4*)(gp + 256);  float4 f1 = *(const float4*)(gp + 260);
    float4 g0 = *(const float4*)(gp + 512);  float4 g1 = *(const float4*)(gp + 516);
    float4 o0 = *(const float4*)(gp + 768);  float4 o1 = *(const float4*)(gp + 772);
    float* cp = g_cc + (size_t)w * 256 + q * 8;
    float4 c0 = *(const float4*)(cp);        float4 c1 = *(const float4*)(cp + 4);
    float gi[8] = {i0.x,i0.y,i0.z,i0.w,i1.x,i1.y,i1.z,i1.w};
    float gf[8] = {f0.x,f0.y,f0.z,f0.w,f1.x,f1.y,f1.z,f1.w};
    float gg[8] = {g0.x,g0.y,g0.z,g0.w,g1.x,g1.y,g1.z,g1.w};
    float go[8] = {o0.x,o0.y,o0.z,o0.w,o1.x,o1.y,o1.z,o1.w};
    float cc[8] = {c0.x,c0.y,c0.z,c0.w,c1.x,c1.y,c1.z,c1.w};
    float h[8];
    #pragma unroll
    for (int j = 0; j < 8; j++) {
        cc[j] = sigm(gf[j]) * cc[j] + sigm(gi[j]) * tanhf(gg[j]);
        h[j] = sigm(go[j]) * tanhf(cc[j]);
    }
    *(float4*)(cp)     = make_float4(cc[0],cc[1],cc[2],cc[3]);
    *(float4*)(cp + 4) = make_float4(cc[4],cc[5],cc[6],cc[7]);
    unsigned short o[24];
    #pragma unroll
    for (int j = 0; j < 8; j++) {
        __nv_bfloat16 hi = __float2bfloat16(h[j]);
        __nv_bfloat16 lo = __float2bfloat16(h[j] - __bfloat162float(hi));
        o[3*j] = __bfloat16_as_ushort(hi);
        o[3*j+1] = __bfloat16_as_ushort(lo);
        o[3*j+2] = __bfloat16_as_ushort(hi);
    }
    uint4* dp = (uint4*)(g_h3 + (size_t)w * 768 + q * 24);
    const uint4* op = (const uint4*)o;
    dp[0] = op[0]; dp[1] = op[1]; dp[2] = op[2];
}

// ==================== mma.sync bf16 GEMM (ldmatrix + swizzle) ====================
#define KT 64

__device__ __forceinline__ void mma16816(float* d, const uint32_t* a, const uint32_t* b) {
    asm volatile(
        "mma.sync.aligned.m16n8k16.row.col.f32.bf16.bf16.f32 "
        "{%0,%1,%2,%3}, {%4,%5,%6,%7}, {%8,%9}, {%0,%1,%2,%3};"
        : "+f"(d[0]), "+f"(d[1]), "+f"(d[2]), "+f"(d[3])
        : "r"(a[0]), "r"(a[1]), "r"(a[2]), "r"(a[3]), "r"(b[0]), "r"(b[1]));
}

#define STAGE_LOAD(s, kt) do {                                                     \
    _Pragma("unroll")                                                              \
    for (int j_ = 0; j_ < 8; j_++) {                                               \
        int ch_ = tid + j_ * 256;                                                  \
        int isB_ = ch_ >> 10, c2_ = ch_ & 1023;                                    \
        int row_ = c2_ >> 3, ck_ = c2_ & 7;                                        \
        const __nv_bfloat16* gp_ = (isB_ ? B + (size_t)(n0 + row_) * K             \
                                         : A + (size_t)(m0 + row_) * K)            \
                                   + (kt) + ck_ * 8;                               \
        uint32_t sp_ = sbase + (s) * 32768 + isB_ * 16384                          \
                     + row_ * 128 + ((ck_ ^ (row_ & 7)) * 16);                     \
        asm volatile("cp.async.cg.shared.global [%0], [%1], 16;"                   \
                     :: "r"(sp_), "l"(gp_));                                       \
    }                                                                              \
    asm volatile("cp.async.commit_group;");                                        \
} while (0)

__global__ __launch_bounds__(256, 2)
void mma_gemm_kernel(const __nv_bfloat16* __restrict__ A,
                     const __nv_bfloat16* __restrict__ B,
                     float* __restrict__ C, int M, int N, int K,
                     const float* __restrict__ bias,
                     const float* __restrict__ addrows,
                     const int* __restrict__ addidx, int idx_stride) {
    extern __shared__ char smraw[];
    uint32_t sb;
    asm("{ .reg .u64 t; cvta.to.shared.u64 t, %1; cvt.u32.u64 %0, t; }"
        : "=r"(sb) : "l"(smraw));
    const uint32_t sbase = (sb + 1023u) & ~1023u;
    const int tid = threadIdx.x;
    const int lane = tid & 31, wid = tid >> 5;
    const int wm = wid >> 2, wn = wid & 3;       // 2 x 4 warp grid
    const int m0 = blockIdx.y * 128, n0 = blockIdx.x * 128;
    const int lrow = lane & 7;
    const int half8 = ((lane >> 3) & 1);
    const int khalf = (lane >> 4);

    float acc[4][4][4];
    #pragma unroll
    for (int i = 0; i < 4; i++)
        #pragma unroll
        for (int j = 0; j < 4; j++)
            #pragma unroll
            for (int q = 0; q < 4; q++) acc[i][j][q] = 0.f;

    STAGE_LOAD(0, 0);
    const int nk = K / KT;
    for (int kt = 0; kt < nk; kt++) {
        if (kt + 1 < nk) {
            STAGE_LOAD((kt + 1) & 1, (kt + 1) * KT);
            asm volatile("cp.async.wait_group 1;");
        } else {
            asm volatile("cp.async.wait_group 0;");
        }
        __syncthreads();

        const uint32_t Abase = sbase + (kt & 1) * 32768;
        const uint32_t Bbase = Abase + 16384;
        #pragma unroll
        for (int k16 = 0; k16 < KT; k16 += 16) {
            const int k8 = k16 >> 3;
            uint32_t a[4][4], b[2][4];
            #pragma unroll
            for (int mi = 0; mi < 4; mi++) {
                int row = wm * 64 + mi * 16 + lrow + half8 * 8;
                uint32_t ad = Abase + row * 128 + (((k8 + khalf) ^ lrow) * 16);
                asm volatile(
                    "ldmatrix.sync.aligned.m8n8.x4.shared.b16 {%0,%1,%2,%3}, [%4];"
                    : "=r"(a[mi][0]), "=r"(a[mi][1]), "=r"(a[mi][2]), "=r"(a[mi][3])
                    : "r"(ad));
            }
            #pragma unroll
            for (int p = 0; p < 2; p++) {
                int nrow = wn * 32 + p * 16 + khalf * 8 + lrow;
                uint32_t bd = Bbase + nrow * 128 + (((k8 + half8) ^ lrow) * 16);
                asm volatile(
                    "ldmatrix.sync.aligned.m8n8.x4.shared.b16 {%0,%1,%2,%3}, [%4];"
                    : "=r"(b[p][0]), "=r"(b[p][1]), "=r"(b[p][2]), "=r"(b[p][3])
                    : "r"(bd));
            }
            #pragma unroll
            for (int mi = 0; mi < 4; mi++)
                #pragma unroll
                for (int p = 0; p < 2; p++) {
                    mma16816(acc[mi][p * 2],     a[mi], &b[p][0]);
                    mma16816(acc[mi][p * 2 + 1], a[mi], &b[p][2]);
                }
        }
        __syncthreads();
    }

    const int r = lane >> 2, cp2 = (lane & 3) * 2;
    #pragma unroll
    for (int mi = 0; mi < 4; mi++) {
        int row0 = m0 + wm * 64 + mi * 16 + r;
        int row1 = row0 + 8;
        const float* ar0 = nullptr;
        const float* ar1 = nullptr;
        if (addrows) {
            ar0 = addrows + (size_t)addidx[(size_t)row0 * idx_stride] * N;
            ar1 = addrows + (size_t)addidx[(size_t)row1 * idx_stride] * N;
        }
        #pragma unroll
        for (int nj = 0; nj < 4; nj++) {
            int col = n0 + wn * 32 + nj * 8 + cp2;
            float v0 = acc[mi][nj][0], v1 = acc[mi][nj][1];
            float v2 = acc[mi][nj][2], v3 = acc[mi][nj][3];
            if (bias) {
                float2 b2 = *(const float2*)(bias + col);
                v0 += b2.x; v1 += b2.y; v2 += b2.x; v3 += b2.y;
            }
            if (ar0) {
                float2 a0 = *(const float2*)(ar0 + col);
                float2 a1 = *(const float2*)(ar1 + col);
                v0 += a0.x; v1 += a0.y; v2 += a1.x; v3 += a1.y;
            }
            *(float2*)(C + (size_t)row0 * N + col) = make_float2(v0, v1);
            *(float2*)(C + (size_t)row1 * N + col) = make_float2(v2, v3);
        }
    }
}
#define GEMM_SMEM (1024 + 2 * 32768)

// ---------------- gather word-LSTM input -> triple bf16 (h part copied from g_h3) ----------------
__global__ void gather_xw3_kernel(const int* __restrict__ word_idx,
                                  const float* __restrict__ word_emb) {
    int idx = blockIdx.x * blockDim.x + threadIdx.x;   // NBS*64, 8 elems each
    int w = idx >> 6, q = idx & 63;
    uint4* dp = (uint4*)(g_xw3 + (size_t)w * 1536 + q * 24);
    if (q < 32) {
        const float* src = word_emb + (size_t)word_idx[w] * NE + q * 8;
        float4 s0 = *(const float4*)(src);
        float4 s1 = *(const float4*)(src + 4);
        float v[8] = {s0.x, s0.y, s0.z, s0.w, s1.x, s1.y, s1.z, s1.w};
        unsigned short o[24];
        #pragma unroll
        for (int j = 0; j < 8; j++) {
            __nv_bfloat16 hi = __float2bfloat16(v[j]);
            __nv_bfloat16 lo = __float2bfloat16(v[j] - __bfloat162float(hi));
            o[3*j] = __bfloat16_as_ushort(hi);
            o[3*j+1] = __bfloat16_as_ushort(lo);
            o[3*j+2] = __bfloat16_as_ushort(hi);
        }
        const uint4* op = (const uint4*)o;
        dp[0] = op[0]; dp[1] = op[1]; dp[2] = op[2];
    } else {
        const uint4* sp = (const uint4*)(g_h3 + (size_t)w * 768 + (q - 32) * 24);
        dp[0] = sp[0]; dp[1] = sp[1]; dp[2] = sp[2];
    }
}

// ---------------- persistent word LSTM v2: 256 thr, split-K halves, split-flag barrier ----------------
// thread (b, ul, half): half-dot over interleaved 4-float chunks k = half*4 + j*8.
// WSTR=HSTR=520 -> weight banks {8ul+4half} and h banks {8b+4half} conflict-free.
#define WSTR 520
#define HSTR 520
__global__ __launch_bounds__(256)
void word_lstm_kernel(const float* __restrict__ Whh) {
    extern __shared__ float sm[];
    float* w_s = sm;                 // [16][WSTR]
    float* h_s = sm + 16 * WSTR;     // [32][HSTR]
    const int tid = threadIdx.x;
    const int b = tid >> 3;          // 0..31
    const int ul = (tid >> 1) & 3;   // 0..3
    const int half = tid & 1;
    const int u = blockIdx.x * 4 + ul;

    for (int i = tid; i < 16 * 512; i += 256) {
        int rr = i >> 9, k = i & 511;
        int grow = (rr >> 2) * NH + blockIdx.x * 4 + (rr & 3);
        w_s[rr * WSTR + k] = Whh[(size_t)grow * NH + k];
    }

    const float* wp0 = w_s + (0 + ul) * WSTR;
    const float* wp1 = w_s + (4 + ul) * WSTR;
    const float* wp2 = w_s + (8 + ul) * WSTR;
    const float* wp3 = w_s + (12 + ul) * WSTR;
    const int kofs = half * 4;

    float c = 0.f;
    unsigned tgt = 0;
    for (int t = 0; t < NS; ++t) {
        if (t == 0) {
            for (int i = tid; i < 32 * 128; i += 256) {
                int bb = i >> 7, kq = i & 127;
                *(float4*)(h_s + bb * HSTR + kq * 4) = make_float4(0, 0, 0, 0);
            }
        } else {
            const float* hp = g_whs + (size_t)(t - 1) * NB * NH;
            for (int i = tid; i < 32 * 128; i += 256) {
                int bb = i >> 7, kq = i & 127;
                *(float4*)(h_s + bb * HSTR + kq * 4) = *(const float4*)(hp + bb * 512 + kq * 4);
            }
        }
        __syncthreads();

        float a0 = 0.f, a1 = 0.f, a2 = 0.f, a3 = 0.f;
        const float* hr = h_s + b * HSTR;
        #pragma unroll 4
        for (int j = 0; j < 64; j++) {
            int k = kofs + j * 8;
            float4 hv = *(const float4*)(hr + k);
            float4 w0 = *(const float4*)(wp0 + k);
            float4 w1 = *(const float4*)(wp1 + k);
            float4 w2 = *(const float4*)(wp2 + k);
            float4 w3 = *(const float4*)(wp3 + k);
            a0 += hv.x * w0.x + hv.y * w0.y + hv.z * w0.z + hv.w * w0.w;
            a1 += hv.x * w1.x + hv.y * w1.y + hv.z * w1.z + hv.w * w1.w;
            a2 += hv.x * w2.x + hv.y * w2.y + hv.z * w2.z + hv.w * w2.w;
            a3 += hv.x * w3.x + hv.y * w3.y + hv.z * w3.z + hv.w * w3.w;
        }
        // pair-reduce halves (partner = tid^1, same warp)
        a0 += __shfl_xor_sync(0xffffffffu, a0, 1);
        a1 += __shfl_xor_sync(0xffffffffu, a1, 1);
        a2 += __shfl_xor_sync(0xffffffffu, a2, 1);
        a3 += __shfl_xor_sync(0xffffffffu, a3, 1);

        const float* gin = g_gin + ((size_t)b * NS + t) * (4 * NH);
        float iv = sigm(a0 + gin[u]);
        float fv = sigm(a1 + gin[NH + u]);
        float gv = tanhf(a2 + gin[2 * NH + u]);
        float ov = sigm(a3 + gin[3 * NH + u]);
        c = fv * c + iv * gv;
        float h = ov * tanhf(c);
        if (half == 0)
            g_whs[(size_t)t * NB * NH + b * NH + u] = h;

        __syncthreads();
        tgt += 128;
        if (tid == 0) {
            __threadfence();
            unsigned old = atomicAdd(&g_bar, 1u);
            if (old == tgt - 1) {
                *((volatile unsigned int*)&g_flag) = (unsigned)(t + 1);
                __threadfence();
            } else {
                while (*((volatile unsigned int*)&g_flag) < (unsigned)(t + 1)) { }
            }
            __threadfence();
        }
        __syncthreads();
    }
}
#define LSTM_SMEM ((16 * WSTR + 32 * HSTR) * 4)   // 99840 B

// ---------------- tag projection + log_softmax ----------------
__global__ void tag_kernel(const float* __restrict__ Wt, const float* __restrict__ bt,
                           float* __restrict__ out) {
    __shared__ float hs[8][512];
    __shared__ float lg[8][52];
    int tid = threadIdx.x, warp = tid >> 5, lane = tid & 31;
    int wbase = blockIdx.x * 8;

    for (int i = tid; i < 8 * 512; i += 256) {
        int tok = i >> 9, k = i & 511;
        int w = wbase + tok;
        int b = w >> 10, s = w & 1023;
        hs[tok][k] = g_whs[((size_t)s * NB + b) * NH + k];
    }
    __syncthreads();

    for (int tg = 0; tg < NT; ++tg) {
        const float* wr = Wt + (size_t)tg * NH;
        float p = 0.f;
        for (int k = lane; k < NH; k += 32) p += hs[warp][k] * wr[k];
        #pragma unroll
        for (int o = 16; o; o >>= 1) p += __shfl_xor_sync(0xffffffff, p, o);
        if (lane == 0) lg[warp][tg] = p + bt[tg];
    }
    __syncwarp();

    float v0 = (lane < NT) ? lg[warp][lane] : -1e30f;
    float v1 = (lane + 32 < NT) ? lg[warp][lane + 32] : -1e30f;
    float m = fmaxf(v0, v1);
    #pragma unroll
    for (int o = 16; o; o >>= 1) m = fmaxf(m, __shfl_xor_sync(0xffffffff, m, o));
    float e = ((lane < NT) ? expf(v0 - m) : 0.f) + ((lane + 32 < NT) ? expf(v1 - m) : 0.f);
    #pragma unroll
    for (int o = 16; o; o >>= 1) e += __shfl_xor_sync(0xffffffff, e, o);
    float lse = m + logf(e);

    int w = wbase + warp;
    if (lane < NT)      out[(size_t)w * NT + lane]      = v0 - lse;
    if (lane + 32 < NT) out[(size_t)w * NT + lane + 32] = v1 - lse;
}

// ---------------- host entry ----------------
extern "C" void kernel_launch(void* const* d_in, const int* in_sizes, int n_in,
                              void* d_out, int out_size) {
    const int*   char_idx = (const int*)d_in[0];
    const int*   word_idx = (const int*)d_in[1];
    const float* char_emb = (const float*)d_in[2];
    const float* word_emb = (const float*)d_in[3];
    const float* Wc_ih    = (const float*)d_in[4];
    const float* Wc_hh    = (const float*)d_in[5];
    const float* bc       = (const float*)d_in[6];
    const float* Ww_ih    = (const float*)d_in[7];
    const float* Ww_hh    = (const float*)d_in[8];
    const float* bw       = (const float*)d_in[9];
    const float* Wt       = (const float*)d_in[10];
    const float* bt       = (const float*)d_in[11];
    float* out = (float*)d_out;

    float *p_gates, *p_gin, *p_cproj;
    __nv_bfloat16 *p_h3, *p_wchh3, *p_xw3, *p_wwih3;
    cudaGetSymbolAddress((void**)&p_gates, g_gates);
    cudaGetSymbolAddress((void**)&p_gin,   g_gin);
    cudaGetSymbolAddress((void**)&p_cproj, g_cproj);
    cudaGetSymbolAddress((void**)&p_h3,    g_h3);
    cudaGetSymbolAddress((void**)&p_wchh3, g_wchh3);
    cudaGetSymbolAddress((void**)&p_xw3,   g_xw3);
    cudaGetSymbolAddress((void**)&p_wwih3, g_wwih3);

    cudaFuncSetAttribute(mma_gemm_kernel,
                         cudaFuncAttributeMaxDynamicSharedMemorySize, GEMM_SMEM);
    cudaFuncSetAttribute(word_lstm_kernel,
                         cudaFuncAttributeMaxDynamicSharedMemorySize, LSTM_SMEM);

    prep_kernel<<<8960, 256>>>(char_emb, Wc_ih, bc, Wc_hh, Ww_ih);           // 1
    gather_gates0_kernel<<<NBS, 256>>>(char_idx);                            // 2
    char_cell_kernel<<<NBS*32/256, 256>>>();                                 // 3
    for (int t = 1; t < NC; t++) {
        mma_gemm_kernel<<<dim3(1024/128, NBS/128), 256, GEMM_SMEM>>>(        // 4 = first
            p_h3, p_wchh3, p_gates, NBS, 1024, 3*NE,
            nullptr, p_cproj, char_idx + t, NC);
        char_cell_kernel<<<NBS*32/256, 256>>>();
    }

    // word input projection
    gather_xw3_kernel<<<NBS*64/256, 256>>>(word_idx, word_emb);
    mma_gemm_kernel<<<dim3(2048/128, NBS/128), 256, GEMM_SMEM>>>(
        p_xw3, p_wwih3, p_gin, NBS, 2048, 3*2*NE,
        bw, nullptr, nullptr, 0);

    // persistent word LSTM v2 (1024 steps, internal grid barrier)
    word_lstm_kernel<<<128, 256, LSTM_SMEM>>>(Ww_hh);

    // tag projection + log_softmax
    tag_kernel<<<NBS/8, 256>>>(Wt, bt, out);
}